// round 8
// baseline (speedup 1.0000x reference)
#include <cuda_runtime.h>
#include <cstdint>
#include <cstddef>

#define B_ROWS 262144
#define TILE_R 64
#define NT     (B_ROWS / TILE_R)   // 4096 CTAs
#define PAD    260                 // padded row stride (floats): mult of 4, ≡4 mod 32
#define CH     32                  // k-chunk staged in smem

// dynamic smem layout: buf[64*PAD] | Ws[CH*PAD]
#define SMEM_BUF_FLOATS (TILE_R * PAD)
#define SMEM_WS_FLOATS  (CH * PAD)
#define SMEM_TOTAL      ((SMEM_BUF_FLOATS + SMEM_WS_FLOATS) * 4)   // 99,840 B

// ---------- packed fp32x2 helpers (IEEE RN per lane; 2x FFMA rate) ----------
__device__ __forceinline__ unsigned long long pack2(float a, float b) {
    unsigned long long d;
    asm("mov.b64 %0, {%1, %2};" : "=l"(d) : "f"(a), "f"(b));
    return d;
}
__device__ __forceinline__ void unpack2(unsigned long long v, float& a, float& b) {
    asm("mov.b64 {%0, %1}, %2;" : "=f"(a), "=f"(b) : "l"(v));
}
__device__ __forceinline__ void ffma2(unsigned long long& d, unsigned long long a, unsigned long long b) {
    asm("fma.rn.f32x2 %0, %1, %2, %0;" : "+l"(d) : "l"(a), "l"(b));
}

// ---------------------------------------------------------------------------
// One GEMM phase: buf[:, 0:256] = relu( buf[:, 0:K] @ W^T + bias ), in place.
// Warp tile: 32 rows x 64 cols. Thread tile: 8 rows (stride 4) x 8 cols.
// Per k-step per warp: 2 LDS wavefronts of B + ~2 of A for 2048 MACs.
// Accumulation order: k ascending (numerics identical to rounds 6/7).
// ---------------------------------------------------------------------------
template<int K>
__device__ __forceinline__ void gemm_phase(const float* __restrict__ W,
                                           const float* __restrict__ bias,
                                           float* __restrict__ buf,
                                           float* __restrict__ Ws,
                                           int tid, int wr, int wc, int ly, int lx)
{
    unsigned long long acc[8][4];
    #pragma unroll
    for (int i = 0; i < 8; ++i)
        #pragma unroll
        for (int m = 0; m < 4; ++m) acc[i][m] = 0ull;

    for (int kc = 0; kc < K; kc += CH) {
        __syncthreads();   // prior readers of Ws done (first chunk: buf staging visible)
        // stage Ws[kk][n] = W[n][kc+kk]  (256 n x 8 float4 along k)
        #pragma unroll
        for (int j = 0; j < 8; ++j) {
            int idx = tid + j * 256;          // 0..2047
            int n  = idx >> 3;
            int f4 = idx & 7;
            float4 w = *(const float4*)(W + (size_t)n * K + kc + f4 * 4);
            Ws[(f4 * 4 + 0) * PAD + n] = w.x;
            Ws[(f4 * 4 + 1) * PAD + n] = w.y;
            Ws[(f4 * 4 + 2) * PAD + n] = w.z;
            Ws[(f4 * 4 + 3) * PAD + n] = w.w;
        }
        __syncthreads();

        #pragma unroll
        for (int kk4 = 0; kk4 < CH / 4; ++kk4) {
            float4 av[8];
            #pragma unroll
            for (int i = 0; i < 8; ++i)
                av[i] = *(const float4*)&buf[(wr + ly + 4 * i) * PAD + kc + kk4 * 4];
            #pragma unroll
            for (int kx = 0; kx < 4; ++kx) {
                int krow = kk4 * 4 + kx;
                float4 w0 = *(const float4*)&Ws[krow * PAD + wc + lx * 8];
                float4 w1 = *(const float4*)&Ws[krow * PAD + wc + lx * 8 + 4];
                unsigned long long bp0 = pack2(w0.x, w0.y);
                unsigned long long bp1 = pack2(w0.z, w0.w);
                unsigned long long bp2 = pack2(w1.x, w1.y);
                unsigned long long bp3 = pack2(w1.z, w1.w);
                #pragma unroll
                for (int i = 0; i < 8; ++i) {
                    float a = (kx == 0) ? av[i].x : (kx == 1) ? av[i].y
                            : (kx == 2) ? av[i].z : av[i].w;
                    unsigned long long ap = pack2(a, a);
                    ffma2(acc[i][0], ap, bp0);
                    ffma2(acc[i][1], ap, bp1);
                    ffma2(acc[i][2], ap, bp2);
                    ffma2(acc[i][3], ap, bp3);
                }
            }
        }
    }

    __syncthreads();   // ALL warps done reading buf before in-place overwrite
    float4 bb0 = *(const float4*)(bias + wc + lx * 8);
    float4 bb1 = *(const float4*)(bias + wc + lx * 8 + 4);
    #pragma unroll
    for (int i = 0; i < 8; ++i) {
        int row = wr + ly + 4 * i;
        float4 r0, r1;
        unpack2(acc[i][0], r0.x, r0.y);
        unpack2(acc[i][1], r0.z, r0.w);
        unpack2(acc[i][2], r1.x, r1.y);
        unpack2(acc[i][3], r1.z, r1.w);
        r0.x = fmaxf(r0.x + bb0.x, 0.f);
        r0.y = fmaxf(r0.y + bb0.y, 0.f);
        r0.z = fmaxf(r0.z + bb0.z, 0.f);
        r0.w = fmaxf(r0.w + bb0.w, 0.f);
        r1.x = fmaxf(r1.x + bb1.x, 0.f);
        r1.y = fmaxf(r1.y + bb1.y, 0.f);
        r1.z = fmaxf(r1.z + bb1.z, 0.f);
        r1.w = fmaxf(r1.w + bb1.w, 0.f);
        *(float4*)&buf[row * PAD + wc + lx * 8]     = r0;
        *(float4*)&buf[row * PAD + wc + lx * 8 + 4] = r1;
    }
}

// ---------------------------------------------------------------------------
// Fully fused actor MLP per CTA: state[64,128] -> h1[64,256] -> h2[64,256]
// -> out[64,8] (float32 values 1.0 .. 9.0). Head replicates XLA fp32
// logistic semantics; decisive 4/5 boundary: v > -3*2^-24 (rel_err 0.0).
// ---------------------------------------------------------------------------
__global__ void __launch_bounds__(256, 2)
actor_fused(const float* __restrict__ state,
            const float* __restrict__ W1, const float* __restrict__ b1,
            const float* __restrict__ W2, const float* __restrict__ b2,
            const float* __restrict__ W3, const float* __restrict__ b3,
            const float* __restrict__ eps, float* __restrict__ out)
{
    extern __shared__ __align__(16) float smem[];
    float* buf = smem;                      // [64][PAD]
    float* Ws  = smem + SMEM_BUF_FLOATS;    // [CH][PAD]  (also holds W3 for head)

    const int tid  = threadIdx.x;
    const int t    = blockIdx.x;
    const int warp = tid >> 5;
    const int lane = tid & 31;
    const int wr   = (warp & 1) * 32;      // warp row offset
    const int wc   = (warp >> 1) * 64;     // warp col offset
    const int ly   = lane >> 3;            // 0..3 (row sub-group, stride 4 rows)
    const int lx   = lane & 7;             // 0..7 (8-col group)

    // ---- load state tile [64][128] into buf ----
    {
        const float4* s4 = (const float4*)(state + (size_t)t * TILE_R * 128);
        #pragma unroll
        for (int j = 0; j < 8; ++j) {
            int idx = tid + j * 256;          // 0..2047 (64 rows x 32 float4)
            int r = idx >> 5, c4 = idx & 31;
            *(float4*)&buf[r * PAD + c4 * 4] = s4[idx];
        }
    }

    // phase 1: h1 = relu(state @ W1^T + b1), K=128
    gemm_phase<128>(W1, b1, buf, Ws, tid, wr, wc, ly, lx);
    // phase 2: h2 = relu(h1 @ W2^T + b2), K=256 (in place)
    gemm_phase<256>(W2, b2, buf, Ws, tid, wr, wc, ly, lx);

    // ================= head =================
    __syncthreads();   // h2 writes visible; Ws free
    // stage W3 [16][256] straight into Ws rows: Ws[j*PAD + k]
    #pragma unroll
    for (int j = 0; j < 4; ++j) {
        int idx = tid + j * 256;              // 0..1023 (16 rows x 64 float4)
        int jr = idx >> 6, k4 = idx & 63;
        *(float4*)&Ws[jr * PAD + k4 * 4] = *(const float4*)(W3 + (size_t)jr * 256 + k4 * 4);
    }
    __syncthreads();

    const int r = tid >> 2;      // row 0..63
    const int q = tid & 3;       // handles output cols q, q+4 (u) / q+8, q+12 (s)

    float d[4] = {0.f, 0.f, 0.f, 0.f};   // dots for jj = q, q+4, q+8, q+12
    #pragma unroll 8
    for (int k4 = 0; k4 < 64; ++k4) {
        float4 h = *(const float4*)&buf[r * PAD + k4 * 4];
        #pragma unroll
        for (int c = 0; c < 4; ++c) {
            int jj = q + 4 * c;
            float4 w = *(const float4*)&Ws[jj * PAD + k4 * 4];
            d[c] = fmaf(h.x, w.x, d[c]);
            d[c] = fmaf(h.y, w.y, d[c]);
            d[c] = fmaf(h.z, w.z, d[c]);
            d[c] = fmaf(h.w, w.w, d[c]);
        }
    }

    const size_t row = (size_t)t * TILE_R + r;
    float u0 = d[0] + b3[q];
    float u1 = d[1] + b3[q + 4];
    float s0 = fabsf(d[2] + b3[q + 8]);
    float s1 = fabsf(d[3] + b3[q + 12]);
    float e0 = eps[row * 8 + q];
    float e1 = eps[row * 8 + q + 4];
    float v0 = fmaf(s0, e0, u0);
    float v1 = fmaf(s1, e1, u1);

    #pragma unroll
    for (int half = 0; half < 2; ++half) {
        float v = half ? v1 : v0;
        int o = 1;
        o += (v > -1.9459101f);
        o += (v > -1.0986123f);
        o += (v > -0.51082563f);
        o += (v > -0x1.8p-23f);      // exact fp32 crossover of sigmoid==0.5
        o += (v >  0.51082563f);
        o += (v >  1.0986123f);
        o += (v >  1.9459101f);
        out[row * 8 + q + 4 * half] = (float)o;
    }
}

// ============================================================================
extern "C" void kernel_launch(void* const* d_in, const int* in_sizes, int n_in,
                              void* d_out, int out_size)
{
    const float* state = nullptr; const float* W1 = nullptr; const float* b1 = nullptr;
    const float* W2 = nullptr;    const float* b2 = nullptr; const float* W3 = nullptr;
    const float* b3 = nullptr;    const float* eps = nullptr;

    for (int pass = 0; pass < 2 && !state; ++pass) {
        long long mul = (pass == 0) ? 1 : 4;
        state = W1 = b1 = W2 = b2 = W3 = b3 = eps = nullptr;
        for (int i = 0; i < n_in; ++i) {
            const float* p = (const float*)d_in[i];
            long long sz = (long long)in_sizes[i];
            if      (sz == 33554432LL * mul) state = p;
            else if (sz == 32768LL    * mul) W1 = p;
            else if (sz == 65536LL    * mul) W2 = p;
            else if (sz == 4096LL     * mul) W3 = p;
            else if (sz == 2097152LL  * mul) eps = p;
            else if (sz == 16LL       * mul) b3 = p;
            else if (sz == 256LL      * mul) { if (!b1) b1 = p; else b2 = p; }
        }
    }
    if (!state || !W1 || !b1 || !W2 || !b2 || !W3 || !b3 || !eps) {
        state = (const float*)d_in[0]; W1 = (const float*)d_in[1];
        b1    = (const float*)d_in[2]; W2 = (const float*)d_in[3];
        b2    = (const float*)d_in[4]; W3 = (const float*)d_in[5];
        b3    = (const float*)d_in[6]; eps = (const float*)d_in[7];
    }

    static bool attr_done = false;
    if (!attr_done) {
        cudaFuncSetAttribute(actor_fused,
                             cudaFuncAttributeMaxDynamicSharedMemorySize, SMEM_TOTAL);
        attr_done = true;
    }

    actor_fused<<<NT, 256, SMEM_TOTAL>>>(state, W1, b1, W2, b2, W3, b3, eps,
                                         (float*)d_out);
}

// round 9
// speedup vs baseline: 1.1456x; 1.1456x over previous
#include <cuda_runtime.h>
#include <cstdint>
#include <cstddef>

#define B_ROWS 262144
#define TILE_R 64
#define NT     (B_ROWS / TILE_R)   // 4096 CTAs
#define PAD    260                 // padded row stride (floats): mult of 4, ≡4 mod 32
#define CH     32                  // k-chunk staged in smem

// dynamic smem layout: buf[64*PAD] | Ws[CH*PAD]
#define SMEM_BUF_FLOATS (TILE_R * PAD)
#define SMEM_WS_FLOATS  (CH * PAD)
#define SMEM_TOTAL      ((SMEM_BUF_FLOATS + SMEM_WS_FLOATS) * 4)   // 99,840 B

// ---------- packed fp32x2 helpers (IEEE RN per lane; 2x FFMA rate) ----------
__device__ __forceinline__ unsigned long long pack2(float a, float b) {
    unsigned long long d;
    asm("mov.b64 %0, {%1, %2};" : "=l"(d) : "f"(a), "f"(b));
    return d;
}
__device__ __forceinline__ void unpack2(unsigned long long v, float& a, float& b) {
    asm("mov.b64 {%0, %1}, %2;" : "=f"(a), "=f"(b) : "l"(v));
}
__device__ __forceinline__ void ffma2(unsigned long long& d, unsigned long long a, unsigned long long b) {
    asm("fma.rn.f32x2 %0, %1, %2, %0;" : "+l"(d) : "l"(a), "l"(b));
}

// ---------------------------------------------------------------------------
// One GEMM phase: buf[:, 0:256] = relu( buf[:, 0:K] @ W^T + bias ), in place.
// Warp tile: 32 rows x 64 cols; thread tile: 8 rows (stride 4) x 8 cols
// (cols lx*4..+3 and lx*4+32..+35 within the warp's 64-col span — both B
// loads span one 32-word bank round -> conflict-free).
// A loaded as float2 per 2 k-steps to keep live registers ~100 (no spills).
// Accumulation: k ascending — bit-identical to rounds 6-8 (rel_err 0.0).
// ---------------------------------------------------------------------------
template<int K>
__device__ __forceinline__ void gemm_phase(const float* __restrict__ W,
                                           const float* __restrict__ bias,
                                           float* __restrict__ buf,
                                           float* __restrict__ Ws,
                                           int tid, int wr, int wc, int ly, int lx)
{
    unsigned long long acc[8][4];   // [row i][col pair]: pairs (g0:lo,hi)(g1:lo,hi)
    #pragma unroll
    for (int i = 0; i < 8; ++i)
        #pragma unroll
        for (int m = 0; m < 4; ++m) acc[i][m] = 0ull;

    const int c0 = wc + lx * 4;          // g=0 col base
    const int c1 = wc + 32 + lx * 4;     // g=1 col base

    for (int kc = 0; kc < K; kc += CH) {
        __syncthreads();   // prior readers of Ws done (first chunk: buf staging visible)
        // stage Ws[kk][n] = W[n][kc+kk]  (256 n x 8 float4 along k)
        #pragma unroll
        for (int j = 0; j < 8; ++j) {
            int idx = tid + j * 256;          // 0..2047
            int n  = idx >> 3;
            int f4 = idx & 7;
            float4 w = *(const float4*)(W + (size_t)n * K + kc + f4 * 4);
            Ws[(f4 * 4 + 0) * PAD + n] = w.x;
            Ws[(f4 * 4 + 1) * PAD + n] = w.y;
            Ws[(f4 * 4 + 2) * PAD + n] = w.z;
            Ws[(f4 * 4 + 3) * PAD + n] = w.w;
        }
        __syncthreads();

        #pragma unroll
        for (int kk2 = 0; kk2 < CH / 2; ++kk2) {
            // A: 8 rows x 2 k as float2 (16 regs)
            float2 av[8];
            #pragma unroll
            for (int i = 0; i < 8; ++i)
                av[i] = *(const float2*)&buf[(wr + ly + 4 * i) * PAD + kc + kk2 * 2];
            #pragma unroll
            for (int kx = 0; kx < 2; ++kx) {
                int krow = kk2 * 2 + kx;
                float4 w0 = *(const float4*)&Ws[krow * PAD + c0];
                float4 w1 = *(const float4*)&Ws[krow * PAD + c1];
                unsigned long long bp0 = pack2(w0.x, w0.y);
                unsigned long long bp1 = pack2(w0.z, w0.w);
                unsigned long long bp2 = pack2(w1.x, w1.y);
                unsigned long long bp3 = pack2(w1.z, w1.w);
                #pragma unroll
                for (int i = 0; i < 8; ++i) {
                    float a = kx ? av[i].y : av[i].x;
                    unsigned long long ap = pack2(a, a);
                    ffma2(acc[i][0], ap, bp0);
                    ffma2(acc[i][1], ap, bp1);
                    ffma2(acc[i][2], ap, bp2);
                    ffma2(acc[i][3], ap, bp3);
                }
            }
        }
    }

    __syncthreads();   // ALL warps done reading buf before in-place overwrite
    float4 bb0 = *(const float4*)(bias + c0);
    float4 bb1 = *(const float4*)(bias + c1);
    #pragma unroll
    for (int i = 0; i < 8; ++i) {
        int row = wr + ly + 4 * i;
        float4 r0, r1;
        unpack2(acc[i][0], r0.x, r0.y);
        unpack2(acc[i][1], r0.z, r0.w);
        unpack2(acc[i][2], r1.x, r1.y);
        unpack2(acc[i][3], r1.z, r1.w);
        r0.x = fmaxf(r0.x + bb0.x, 0.f);
        r0.y = fmaxf(r0.y + bb0.y, 0.f);
        r0.z = fmaxf(r0.z + bb0.z, 0.f);
        r0.w = fmaxf(r0.w + bb0.w, 0.f);
        r1.x = fmaxf(r1.x + bb1.x, 0.f);
        r1.y = fmaxf(r1.y + bb1.y, 0.f);
        r1.z = fmaxf(r1.z + bb1.z, 0.f);
        r1.w = fmaxf(r1.w + bb1.w, 0.f);
        *(float4*)&buf[row * PAD + c0] = r0;
        *(float4*)&buf[row * PAD + c1] = r1;
    }
}

// ---------------------------------------------------------------------------
// Fully fused actor MLP per CTA: state[64,128] -> h1[64,256] -> h2[64,256]
// -> out[64,8] (float32 values 1.0 .. 9.0). Head replicates XLA fp32
// logistic semantics; decisive 4/5 boundary: v > -3*2^-24 (rel_err 0.0).
// ---------------------------------------------------------------------------
__global__ void __launch_bounds__(256, 2)
actor_fused(const float* __restrict__ state,
            const float* __restrict__ W1, const float* __restrict__ b1,
            const float* __restrict__ W2, const float* __restrict__ b2,
            const float* __restrict__ W3, const float* __restrict__ b3,
            const float* __restrict__ eps, float* __restrict__ out)
{
    extern __shared__ __align__(16) float smem[];
    float* buf = smem;                      // [64][PAD]
    float* Ws  = smem + SMEM_BUF_FLOATS;    // [CH][PAD]  (also holds W3 for head)

    const int tid  = threadIdx.x;
    const int t    = blockIdx.x;
    const int warp = tid >> 5;
    const int lane = tid & 31;
    const int wr   = (warp & 1) * 32;      // warp row offset
    const int wc   = (warp >> 1) * 64;     // warp col offset
    const int ly   = lane >> 3;            // 0..3 (row sub-group, stride 4)
    const int lx   = lane & 7;             // 0..7 (4-col group)

    // ---- load state tile [64][128] into buf ----
    {
        const float4* s4 = (const float4*)(state + (size_t)t * TILE_R * 128);
        #pragma unroll
        for (int j = 0; j < 8; ++j) {
            int idx = tid + j * 256;          // 0..2047 (64 rows x 32 float4)
            int r = idx >> 5, c4 = idx & 31;
            *(float4*)&buf[r * PAD + c4 * 4] = s4[idx];
        }
    }

    // phase 1: h1 = relu(state @ W1^T + b1), K=128
    gemm_phase<128>(W1, b1, buf, Ws, tid, wr, wc, ly, lx);
    // phase 2: h2 = relu(h1 @ W2^T + b2), K=256 (in place)
    gemm_phase<256>(W2, b2, buf, Ws, tid, wr, wc, ly, lx);

    // ================= head =================
    __syncthreads();   // h2 writes visible; Ws free
    // stage W3 [16][256] straight into Ws rows: Ws[j*PAD + k]
    #pragma unroll
    for (int j = 0; j < 4; ++j) {
        int idx = tid + j * 256;              // 0..1023 (16 rows x 64 float4)
        int jr = idx >> 6, k4 = idx & 63;
        *(float4*)&Ws[jr * PAD + k4 * 4] = *(const float4*)(W3 + (size_t)jr * 256 + k4 * 4);
    }
    __syncthreads();

    const int r = tid >> 2;      // row 0..63
    const int q = tid & 3;       // handles output cols q, q+4 (u) / q+8, q+12 (s)

    float d[4] = {0.f, 0.f, 0.f, 0.f};   // dots for jj = q, q+4, q+8, q+12
    #pragma unroll 8
    for (int k4 = 0; k4 < 64; ++k4) {
        float4 h = *(const float4*)&buf[r * PAD + k4 * 4];
        #pragma unroll
        for (int c = 0; c < 4; ++c) {
            int jj = q + 4 * c;
            float4 w = *(const float4*)&Ws[jj * PAD + k4 * 4];
            d[c] = fmaf(h.x, w.x, d[c]);
            d[c] = fmaf(h.y, w.y, d[c]);
            d[c] = fmaf(h.z, w.z, d[c]);
            d[c] = fmaf(h.w, w.w, d[c]);
        }
    }

    const size_t row = (size_t)t * TILE_R + r;
    float u0 = d[0] + b3[q];
    float u1 = d[1] + b3[q + 4];
    float s0 = fabsf(d[2] + b3[q + 8]);
    float s1 = fabsf(d[3] + b3[q + 12]);
    float e0 = eps[row * 8 + q];
    float e1 = eps[row * 8 + q + 4];
    float v0 = fmaf(s0, e0, u0);
    float v1 = fmaf(s1, e1, u1);

    #pragma unroll
    for (int half = 0; half < 2; ++half) {
        float v = half ? v1 : v0;
        int o = 1;
        o += (v > -1.9459101f);
        o += (v > -1.0986123f);
        o += (v > -0.51082563f);
        o += (v > -0x1.8p-23f);      // exact fp32 crossover of sigmoid==0.5
        o += (v >  0.51082563f);
        o += (v >  1.0986123f);
        o += (v >  1.9459101f);
        out[row * 8 + q + 4 * half] = (float)o;
    }
}

// ============================================================================
extern "C" void kernel_launch(void* const* d_in, const int* in_sizes, int n_in,
                              void* d_out, int out_size)
{
    const float* state = nullptr; const float* W1 = nullptr; const float* b1 = nullptr;
    const float* W2 = nullptr;    const float* b2 = nullptr; const float* W3 = nullptr;
    const float* b3 = nullptr;    const float* eps = nullptr;

    for (int pass = 0; pass < 2 && !state; ++pass) {
        long long mul = (pass == 0) ? 1 : 4;
        state = W1 = b1 = W2 = b2 = W3 = b3 = eps = nullptr;
        for (int i = 0; i < n_in; ++i) {
            const float* p = (const float*)d_in[i];
            long long sz = (long long)in_sizes[i];
            if      (sz == 33554432LL * mul) state = p;
            else if (sz == 32768LL    * mul) W1 = p;
            else if (sz == 65536LL    * mul) W2 = p;
            else if (sz == 4096LL     * mul) W3 = p;
            else if (sz == 2097152LL  * mul) eps = p;
            else if (sz == 16LL       * mul) b3 = p;
            else if (sz == 256LL      * mul) { if (!b1) b1 = p; else b2 = p; }
        }
    }
    if (!state || !W1 || !b1 || !W2 || !b2 || !W3 || !b3 || !eps) {
        state = (const float*)d_in[0]; W1 = (const float*)d_in[1];
        b1    = (const float*)d_in[2]; W2 = (const float*)d_in[3];
        b2    = (const float*)d_in[4]; W3 = (const float*)d_in[5];
        b3    = (const float*)d_in[6]; eps = (const float*)d_in[7];
    }

    static bool attr_done = false;
    if (!attr_done) {
        cudaFuncSetAttribute(actor_fused,
                             cudaFuncAttributeMaxDynamicSharedMemorySize, SMEM_TOTAL);
        attr_done = true;
    }

    actor_fused<<<NT, 256, SMEM_TOTAL>>>(state, W1, b1, W2, b2, W3, b3, eps,
                                         (float*)d_out);
}

// round 10
// speedup vs baseline: 1.2109x; 1.0570x over previous
#include <cuda_runtime.h>
#include <cstdint>
#include <cstddef>

#define B_ROWS 262144
#define TILE_R 64
#define NT     (B_ROWS / TILE_R)   // 4096 CTAs
#define PAD    260                 // buf row stride (floats)
#define CH     16                  // k-chunk staged per barrier
#define SNW    264                 // Whi/Wlo k-row stride: 264%32==8 -> B-frag loads hit 32 distinct banks

#define SMEM_BUF_FLOATS (TILE_R * PAD)      // 16640
#define SMEM_W_FLOATS   (CH * SNW)          // 4224 (each of hi/lo)
#define SMEM_TOTAL      ((SMEM_BUF_FLOATS + 2 * SMEM_W_FLOATS) * 4)   // 100,352 B

// ---------- tf32 split: x == hi + lo to ~24 mantissa bits ----------
__device__ __forceinline__ void split_tf32(float x, uint32_t& hi, uint32_t& lo) {
    asm("cvt.rna.tf32.f32 %0, %1;" : "=r"(hi) : "f"(x));
    float r = x - __uint_as_float(hi);   // exact (Sterbenz)
    asm("cvt.rna.tf32.f32 %0, %1;" : "=r"(lo) : "f"(r));
}

// ---------- warp-level tensor MMA: D(16x8) += A(16x8,tf32) B(8x8,tf32) ----------
__device__ __forceinline__ void mma_tf32(float c[4], const uint32_t a[4],
                                         uint32_t b0, uint32_t b1) {
    asm volatile(
        "mma.sync.aligned.m16n8k8.row.col.f32.tf32.tf32.f32 "
        "{%0,%1,%2,%3},{%4,%5,%6,%7},{%8,%9},{%0,%1,%2,%3};"
        : "+f"(c[0]), "+f"(c[1]), "+f"(c[2]), "+f"(c[3])
        : "r"(a[0]), "r"(a[1]), "r"(a[2]), "r"(a[3]), "r"(b0), "r"(b1));
}

// ---------------------------------------------------------------------------
// One GEMM phase on tensor cores (3xTF32 ~ fp32 accuracy):
//   buf[:, 0:256] = relu( buf[:, 0:K] @ W^T + bias ), in place.
// Warp tile: 32 rows x 64 cols = 2 m16 tiles x 8 n8 tiles; 3 MMAs per tile
// per k8 (hi*hi, lo*hi, hi*lo). Weights split to tf32 hi/lo at chunk staging.
// ---------------------------------------------------------------------------
template<int K>
__device__ __forceinline__ void gemm_tc(const float* __restrict__ W,
                                        const float* __restrict__ bias,
                                        float* __restrict__ buf,
                                        float* __restrict__ Whi,
                                        float* __restrict__ Wlo,
                                        int tid, int wr0, int wc0, int g, int tg)
{
    float c[2][8][4];
    #pragma unroll
    for (int i = 0; i < 2; ++i)
        #pragma unroll
        for (int j = 0; j < 8; ++j)
            #pragma unroll
            for (int q = 0; q < 4; ++q) c[i][j][q] = 0.f;

    for (int kc = 0; kc < K; kc += CH) {
        __syncthreads();   // prior readers of Whi/Wlo done (first chunk: buf staging visible)
        // stage: thread tid owns weight row n=tid, k in [kc, kc+CH)
        {
            const float* wrow = W + (size_t)tid * K + kc;
            #pragma unroll
            for (int f4 = 0; f4 < CH / 4; ++f4) {
                float4 w = *(const float4*)(wrow + f4 * 4);
                float e[4] = {w.x, w.y, w.z, w.w};
                #pragma unroll
                for (int q = 0; q < 4; ++q) {
                    uint32_t hi, lo;
                    split_tf32(e[q], hi, lo);
                    Whi[(f4 * 4 + q) * SNW + tid] = __uint_as_float(hi);
                    Wlo[(f4 * 4 + q) * SNW + tid] = __uint_as_float(lo);
                }
            }
        }
        __syncthreads();

        #pragma unroll
        for (int k8 = 0; k8 < CH; k8 += 8) {
            // A fragments for the 2 m16 tiles, split on the fly
            uint32_t ahi[2][4], alo[2][4];
            #pragma unroll
            for (int i = 0; i < 2; ++i) {
                int r0 = wr0 + 16 * i + g;
                int kk = kc + k8 + tg;
                split_tf32(buf[r0 * PAD + kk],           ahi[i][0], alo[i][0]);
                split_tf32(buf[(r0 + 8) * PAD + kk],     ahi[i][1], alo[i][1]);
                split_tf32(buf[r0 * PAD + kk + 4],       ahi[i][2], alo[i][2]);
                split_tf32(buf[(r0 + 8) * PAD + kk + 4], ahi[i][3], alo[i][3]);
            }
            #pragma unroll
            for (int j = 0; j < 8; ++j) {
                int n  = wc0 + 8 * j + g;
                int kb = k8 + tg;
                uint32_t bh0 = __float_as_uint(Whi[kb * SNW + n]);
                uint32_t bh1 = __float_as_uint(Whi[(kb + 4) * SNW + n]);
                uint32_t bl0 = __float_as_uint(Wlo[kb * SNW + n]);
                uint32_t bl1 = __float_as_uint(Wlo[(kb + 4) * SNW + n]);
                #pragma unroll
                for (int i = 0; i < 2; ++i) {
                    mma_tf32(c[i][j], ahi[i], bh0, bh1);   // hi*hi
                    mma_tf32(c[i][j], alo[i], bh0, bh1);   // lo*hi
                    mma_tf32(c[i][j], ahi[i], bl0, bl1);   // hi*lo
                }
            }
        }
    }

    __syncthreads();   // ALL warps done reading buf before in-place overwrite
    #pragma unroll
    for (int i = 0; i < 2; ++i) {
        int r0 = wr0 + 16 * i + g;
        #pragma unroll
        for (int j = 0; j < 8; ++j) {
            int col = wc0 + 8 * j + 2 * tg;
            float2 bb = *(const float2*)(bias + col);
            float v0 = fmaxf(c[i][j][0] + bb.x, 0.f);
            float v1 = fmaxf(c[i][j][1] + bb.y, 0.f);
            float v2 = fmaxf(c[i][j][2] + bb.x, 0.f);
            float v3 = fmaxf(c[i][j][3] + bb.y, 0.f);
            *(float2*)&buf[r0 * PAD + col]       = make_float2(v0, v1);
            *(float2*)&buf[(r0 + 8) * PAD + col] = make_float2(v2, v3);
        }
    }
}

// ---------------------------------------------------------------------------
// Fused actor MLP per CTA: state[64,128] -> h1[64,256] -> h2[64,256] -> out[64,8]
// (float32 values 1.0 .. 9.0). GEMMs on tensor cores (3xTF32); head exact fp32.
// Decisive 4/5 boundary: v > -3*2^-24 (XLA logistic crossover).
// ---------------------------------------------------------------------------
__global__ void __launch_bounds__(256, 2)
actor_fused(const float* __restrict__ state,
            const float* __restrict__ W1, const float* __restrict__ b1,
            const float* __restrict__ W2, const float* __restrict__ b2,
            const float* __restrict__ W3, const float* __restrict__ b3,
            const float* __restrict__ eps, float* __restrict__ out)
{
    extern __shared__ __align__(16) float smem[];
    float* buf = smem;                                    // [64][PAD]
    float* Whi = smem + SMEM_BUF_FLOATS;                  // [CH][SNW]
    float* Wlo = smem + SMEM_BUF_FLOATS + SMEM_W_FLOATS;  // [CH][SNW]

    const int tid  = threadIdx.x;
    const int t    = blockIdx.x;
    const int warp = tid >> 5;
    const int lane = tid & 31;
    const int wr0  = (warp & 1) * 32;      // warp row offset (2 groups)
    const int wc0  = (warp >> 1) * 64;     // warp col offset (4 groups)
    const int g    = lane >> 2;            // 0..7
    const int tg   = lane & 3;             // 0..3

    // ---- load state tile [64][128] into buf ----
    {
        const float4* s4 = (const float4*)(state + (size_t)t * TILE_R * 128);
        #pragma unroll
        for (int j = 0; j < 8; ++j) {
            int idx = tid + j * 256;          // 0..2047 (64 rows x 32 float4)
            int r = idx >> 5, c4 = idx & 31;
            *(float4*)&buf[r * PAD + c4 * 4] = s4[idx];
        }
    }

    // phase 1: h1 = relu(state @ W1^T + b1), K=128  (tensor cores)
    gemm_tc<128>(W1, b1, buf, Whi, Wlo, tid, wr0, wc0, g, tg);
    // phase 2: h2 = relu(h1 @ W2^T + b2), K=256    (tensor cores, in place)
    gemm_tc<256>(W2, b2, buf, Whi, Wlo, tid, wr0, wc0, g, tg);

    // ================= head (exact fp32 scalar) =================
    __syncthreads();   // h2 visible; W staging area free
    // stage W3 [16][256] with stride 260 (bank-spread): Ws[jr*260 + k]
    float* Ws = Whi;   // 16*260 = 4160 <= 4224 floats
    #pragma unroll
    for (int j = 0; j < 4; ++j) {
        int idx = tid + j * 256;              // 0..1023 (16 rows x 64 float4)
        int jr = idx >> 6, k4 = idx & 63;
        *(float4*)&Ws[jr * 260 + k4 * 4] = *(const float4*)(W3 + (size_t)jr * 256 + k4 * 4);
    }
    __syncthreads();

    const int r = tid >> 2;      // row 0..63
    const int q = tid & 3;       // output cols q, q+4 (u) / q+8, q+12 (s)

    float d[4] = {0.f, 0.f, 0.f, 0.f};
    #pragma unroll 8
    for (int k4 = 0; k4 < 64; ++k4) {
        float4 h = *(const float4*)&buf[r * PAD + k4 * 4];
        #pragma unroll
        for (int cidx = 0; cidx < 4; ++cidx) {
            int jj = q + 4 * cidx;
            float4 w = *(const float4*)&Ws[jj * 260 + k4 * 4];
            d[cidx] = fmaf(h.x, w.x, d[cidx]);
            d[cidx] = fmaf(h.y, w.y, d[cidx]);
            d[cidx] = fmaf(h.z, w.z, d[cidx]);
            d[cidx] = fmaf(h.w, w.w, d[cidx]);
        }
    }

    const size_t row = (size_t)t * TILE_R + r;
    float u0 = d[0] + b3[q];
    float u1 = d[1] + b3[q + 4];
    float s0 = fabsf(d[2] + b3[q + 8]);
    float s1 = fabsf(d[3] + b3[q + 12]);
    float e0 = eps[row * 8 + q];
    float e1 = eps[row * 8 + q + 4];
    float v0 = fmaf(s0, e0, u0);
    float v1 = fmaf(s1, e1, u1);

    #pragma unroll
    for (int half = 0; half < 2; ++half) {
        float v = half ? v1 : v0;
        int o = 1;
        o += (v > -1.9459101f);
        o += (v > -1.0986123f);
        o += (v > -0.51082563f);
        o += (v > -0x1.8p-23f);      // exact fp32 crossover of sigmoid==0.5
        o += (v >  0.51082563f);
        o += (v >  1.0986123f);
        o += (v >  1.9459101f);
        out[row * 8 + q + 4 * half] = (float)o;
    }
}

// ============================================================================
extern "C" void kernel_launch(void* const* d_in, const int* in_sizes, int n_in,
                              void* d_out, int out_size)
{
    const float* state = nullptr; const float* W1 = nullptr; const float* b1 = nullptr;
    const float* W2 = nullptr;    const float* b2 = nullptr; const float* W3 = nullptr;
    const float* b3 = nullptr;    const float* eps = nullptr;

    for (int pass = 0; pass < 2 && !state; ++pass) {
        long long mul = (pass == 0) ? 1 : 4;
        state = W1 = b1 = W2 = b2 = W3 = b3 = eps = nullptr;
        for (int i = 0; i < n_in; ++i) {
            const float* p = (const float*)d_in[i];
            long long sz = (long long)in_sizes[i];
            if      (sz == 33554432LL * mul) state = p;
            else if (sz == 32768LL    * mul) W1 = p;
            else if (sz == 65536LL    * mul) W2 = p;
            else if (sz == 4096LL     * mul) W3 = p;
            else if (sz == 2097152LL  * mul) eps = p;
            else if (sz == 16LL       * mul) b3 = p;
            else if (sz == 256LL      * mul) { if (!b1) b1 = p; else b2 = p; }
        }
    }
    if (!state || !W1 || !b1 || !W2 || !b2 || !W3 || !b3 || !eps) {
        state = (const float*)d_in[0]; W1 = (const float*)d_in[1];
        b1    = (const float*)d_in[2]; W2 = (const float*)d_in[3];
        b2    = (const float*)d_in[4]; W3 = (const float*)d_in[5];
        b3    = (const float*)d_in[6]; eps = (const float*)d_in[7];
    }

    static bool attr_done = false;
    if (!attr_done) {
        cudaFuncSetAttribute(actor_fused,
                             cudaFuncAttributeMaxDynamicSharedMemorySize, SMEM_TOTAL);
        attr_done = true;
    }

    actor_fused<<<NT, 256, SMEM_TOTAL>>>(state, W1, b1, W2, b2, W3, b3, eps,
                                         (float*)d_out);
}

// round 11
// speedup vs baseline: 1.5212x; 1.2562x over previous
#include <cuda_runtime.h>
#include <cstdint>
#include <cstddef>

#define B_ROWS 262144
#define TILE_R 64
#define NT     (B_ROWS / TILE_R)   // 4096 CTAs
#define PAD    260                 // buf row stride (floats)

#define NBLK1  16                  // layer-1 k8 blocks (K=128)
#define NBLK2  32                  // layer-2 k8 blocks (K=256)
#define NBLK   (NBLK1 + NBLK2)     // 48
#define TG_F4  258                 // float4 stride between tg rows (bank spread: 8 mod 32 words)
#define BLK_F4 (4 * TG_F4)         // 1032 float4 per block
#define BLK_BYTES (BLK_F4 * 16)    // 16512

// smem: buf[64*PAD] | Wf[2 slots * BLK_F4 float4] | 2 mbarriers
#define BUF_F      (TILE_R * PAD)          // 16640 floats
#define WF_F       (2 * BLK_F4 * 4)        // 8256 floats
#define MBAR_BYTE  ((BUF_F + WF_F) * 4)    // 99584 (8-aligned)
#define SMEM_TOTAL (MBAR_BYTE + 16)        // 99600 B

// Pre-split, fragment-packed weights (written by prep kernel):
// block bi, frag[tg][n] = {hi(k), hi(k+4), lo(k), lo(k+4)}, k = 8*bi_local + tg
__device__ __align__(16) float4 g_Wpk[NBLK * BLK_F4];

// ---------- tf32 split ----------
__device__ __forceinline__ void split_tf32(float x, uint32_t& hi, uint32_t& lo) {
    asm("cvt.rna.tf32.f32 %0, %1;" : "=r"(hi) : "f"(x));
    float r = x - __uint_as_float(hi);
    asm("cvt.rna.tf32.f32 %0, %1;" : "=r"(lo) : "f"(r));
}

// ---------- warp MMA m16n8k8 tf32 ----------
__device__ __forceinline__ void mma_tf32(float c[4], const uint32_t a[4],
                                         uint32_t b0, uint32_t b1) {
    asm volatile(
        "mma.sync.aligned.m16n8k8.row.col.f32.tf32.tf32.f32 "
        "{%0,%1,%2,%3},{%4,%5,%6,%7},{%8,%9},{%0,%1,%2,%3};"
        : "+f"(c[0]), "+f"(c[1]), "+f"(c[2]), "+f"(c[3])
        : "r"(a[0]), "r"(a[1]), "r"(a[2]), "r"(a[3]), "r"(b0), "r"(b1));
}

// ---------- mbarrier + 1D bulk copy ----------
__device__ __forceinline__ void mbar_init(uint32_t a, uint32_t cnt) {
    asm volatile("mbarrier.init.shared.b64 [%0], %1;" :: "r"(a), "r"(cnt) : "memory");
}
__device__ __forceinline__ void mbar_expect(uint32_t a, uint32_t bytes) {
    asm volatile("mbarrier.arrive.expect_tx.shared.b64 _, [%0], %1;" :: "r"(a), "r"(bytes) : "memory");
}
__device__ __forceinline__ void mbar_wait(uint32_t a, uint32_t parity) {
    asm volatile(
        "{\n\t.reg .pred P;\n"
        "W%=:\n\t"
        "mbarrier.try_wait.parity.acquire.cta.shared::cta.b64 P, [%0], %1, 0x989680;\n\t"
        "@P bra D%=;\n\t"
        "bra W%=;\n"
        "D%=:\n\t}"
        :: "r"(a), "r"(parity) : "memory");
}
__device__ __forceinline__ void bulk_g2s(uint32_t dst, const void* src,
                                         uint32_t bytes, uint32_t mbar) {
    asm volatile(
        "cp.async.bulk.shared::cta.global.mbarrier::complete_tx::bytes [%0], [%1], %2, [%3];"
        :: "r"(dst), "l"(src), "r"(bytes), "r"(mbar) : "memory");
}

// ============================================================================
// Prep kernel: split W into tf32 hi/lo and pack fragment-ready blocks.
// grid = NBLK blocks, 256 threads; thread = output row n, block = k8 index.
// ============================================================================
__global__ void prep_w(const float* __restrict__ W1, const float* __restrict__ W2)
{
    const int bi = blockIdx.x;        // 0..47
    const int n  = threadIdx.x;       // 0..255
    const float* W = (bi < NBLK1) ? W1 : W2;
    const int K    = (bi < NBLK1) ? 128 : 256;
    const int kloc = (bi < NBLK1) ? bi * 8 : (bi - NBLK1) * 8;

    const float* src = W + (size_t)n * K + kloc;
    float e[8];
    *(float4*)&e[0] = *(const float4*)(src);
    *(float4*)&e[4] = *(const float4*)(src + 4);
    uint32_t hi[8], lo[8];
    #pragma unroll
    for (int i = 0; i < 8; ++i) split_tf32(e[i], hi[i], lo[i]);

    #pragma unroll
    for (int tg = 0; tg < 4; ++tg) {
        float4 f;
        f.x = __uint_as_float(hi[tg]);
        f.y = __uint_as_float(hi[tg + 4]);
        f.z = __uint_as_float(lo[tg]);
        f.w = __uint_as_float(lo[tg + 4]);
        g_Wpk[bi * BLK_F4 + tg * TG_F4 + n] = f;
    }
}

// ============================================================================
// Main fused kernel. Warp = 64 rows x 32 cols (4 m16 x 4 n8 tiles).
// ============================================================================
__global__ void __launch_bounds__(256, 2)
actor_fused(const float* __restrict__ state,
            const float* __restrict__ b1, const float* __restrict__ b2,
            const float* __restrict__ W3, const float* __restrict__ b3,
            const float* __restrict__ eps, float* __restrict__ out)
{
    extern __shared__ __align__(16) float smem[];
    float* buf     = smem;                 // [64][PAD]
    float* wfbase  = smem + BUF_F;         // 2 slots of BLK_F4 float4
    const uint32_t smem_u32 = (uint32_t)__cvta_generic_to_shared(smem);
    const uint32_t wf_u32   = smem_u32 + BUF_F * 4;
    const uint32_t mb[2]    = { smem_u32 + MBAR_BYTE, smem_u32 + MBAR_BYTE + 8 };

    const int tid  = threadIdx.x;
    const int t    = blockIdx.x;
    const int warp = tid >> 5;
    const int lane = tid & 31;
    const int wc0  = warp * 32;           // warp col offset (8 groups x 32 cols)
    const int g    = lane >> 2;           // 0..7
    const int tg   = lane & 3;            // 0..3

    // init barriers + kick off first two weight blocks
    if (tid == 0) {
        mbar_init(mb[0], 1);
        mbar_init(mb[1], 1);
        asm volatile("fence.proxy.async.shared::cta;" ::: "memory");
        mbar_expect(mb[0], BLK_BYTES);
        bulk_g2s(wf_u32,             g_Wpk,          BLK_BYTES, mb[0]);
        mbar_expect(mb[1], BLK_BYTES);
        bulk_g2s(wf_u32 + BLK_BYTES, g_Wpk + BLK_F4, BLK_BYTES, mb[1]);
    }

    // load state tile [64][128] (overlaps with the bulk copies)
    {
        const float4* s4 = (const float4*)(state + (size_t)t * TILE_R * 128);
        #pragma unroll
        for (int j = 0; j < 8; ++j) {
            int idx = tid + j * 256;
            int r = idx >> 5, c4 = idx & 31;
            *(float4*)&buf[r * PAD + c4 * 4] = s4[idx];
        }
    }
    __syncthreads();   // state tile + barrier init visible

    // ---- two GEMM phases ----
    #pragma unroll 1
    for (int phase = 0; phase < 2; ++phase) {
        const int b0 = phase ? NBLK1 : 0;
        const int nb = phase ? NBLK2 : NBLK1;
        const float* bias = phase ? b2 : b1;

        float c[4][4][4];
        #pragma unroll
        for (int i = 0; i < 4; ++i)
            #pragma unroll
            for (int j = 0; j < 4; ++j)
                #pragma unroll
                for (int q = 0; q < 4; ++q) c[i][j][q] = 0.f;

        #pragma unroll 1
        for (int ib = 0; ib < nb; ++ib) {
            const int bi = b0 + ib;
            mbar_wait(mb[bi & 1], (bi >> 1) & 1);

            const float* Wf = wfbase + (size_t)(bi & 1) * BLK_F4 * 4;
            float4 Bf[4];
            #pragma unroll
            for (int j = 0; j < 4; ++j)
                Bf[j] = *(const float4*)&Wf[(tg * TG_F4 + wc0 + 8 * j + g) * 4];

            const int kb = ib * 8;
            #pragma unroll
            for (int i = 0; i < 4; ++i) {
                int r0 = 16 * i + g;
                uint32_t ahi[4], alo[4];
                split_tf32(buf[r0 * PAD + kb + tg],           ahi[0], alo[0]);
                split_tf32(buf[(r0 + 8) * PAD + kb + tg],     ahi[1], alo[1]);
                split_tf32(buf[r0 * PAD + kb + tg + 4],       ahi[2], alo[2]);
                split_tf32(buf[(r0 + 8) * PAD + kb + tg + 4], ahi[3], alo[3]);
                #pragma unroll
                for (int j = 0; j < 4; ++j) {
                    uint32_t bh0 = __float_as_uint(Bf[j].x), bh1 = __float_as_uint(Bf[j].y);
                    uint32_t bl0 = __float_as_uint(Bf[j].z), bl1 = __float_as_uint(Bf[j].w);
                    mma_tf32(c[i][j], ahi, bh0, bh1);   // hi*hi
                    mma_tf32(c[i][j], alo, bh0, bh1);   // lo*hi
                    mma_tf32(c[i][j], ahi, bl0, bl1);   // hi*lo
                }
            }

            __syncthreads();   // all warps done with this slot (and prior buf reads)
            if (tid == 0 && bi + 2 < NBLK) {
                mbar_expect(mb[bi & 1], BLK_BYTES);
                bulk_g2s(wf_u32 + (uint32_t)(bi & 1) * BLK_BYTES,
                         g_Wpk + (size_t)(bi + 2) * BLK_F4, BLK_BYTES, mb[bi & 1]);
            }
        }

        // epilogue: bias + relu, in place (last loop iteration ended with sync)
        #pragma unroll
        for (int i = 0; i < 4; ++i) {
            int r0 = 16 * i + g;
            #pragma unroll
            for (int j = 0; j < 4; ++j) {
                int col = wc0 + 8 * j + 2 * tg;
                float2 bb = *(const float2*)(bias + col);
                float v0 = fmaxf(c[i][j][0] + bb.x, 0.f);
                float v1 = fmaxf(c[i][j][1] + bb.y, 0.f);
                float v2 = fmaxf(c[i][j][2] + bb.x, 0.f);
                float v3 = fmaxf(c[i][j][3] + bb.y, 0.f);
                *(float2*)&buf[r0 * PAD + col]       = make_float2(v0, v1);
                *(float2*)&buf[(r0 + 8) * PAD + col] = make_float2(v2, v3);
            }
        }
        __syncthreads();   // updated buf visible before next phase / head
    }

    // ================= head (exact fp32 scalar) =================
    float* Ws = wfbase;   // 16*260 = 4160 floats, fits in slot area
    #pragma unroll
    for (int j = 0; j < 4; ++j) {
        int idx = tid + j * 256;              // 16 rows x 64 float4
        int jr = idx >> 6, k4 = idx & 63;
        *(float4*)&Ws[jr * 260 + k4 * 4] = *(const float4*)(W3 + (size_t)jr * 256 + k4 * 4);
    }
    __syncthreads();

    const int r = tid >> 2;
    const int q = tid & 3;

    float d[4] = {0.f, 0.f, 0.f, 0.f};
    #pragma unroll 8
    for (int k4 = 0; k4 < 64; ++k4) {
        float4 h = *(const float4*)&buf[r * PAD + k4 * 4];
        #pragma unroll
        for (int cidx = 0; cidx < 4; ++cidx) {
            int jj = q + 4 * cidx;
            float4 w = *(const float4*)&Ws[jj * 260 + k4 * 4];
            d[cidx] = fmaf(h.x, w.x, d[cidx]);
            d[cidx] = fmaf(h.y, w.y, d[cidx]);
            d[cidx] = fmaf(h.z, w.z, d[cidx]);
            d[cidx] = fmaf(h.w, w.w, d[cidx]);
        }
    }

    const size_t row = (size_t)t * TILE_R + r;
    float u0 = d[0] + b3[q];
    float u1 = d[1] + b3[q + 4];
    float s0 = fabsf(d[2] + b3[q + 8]);
    float s1 = fabsf(d[3] + b3[q + 12]);
    float e0 = eps[row * 8 + q];
    float e1 = eps[row * 8 + q + 4];
    float v0 = fmaf(s0, e0, u0);
    float v1 = fmaf(s1, e1, u1);

    #pragma unroll
    for (int half = 0; half < 2; ++half) {
        float v = half ? v1 : v0;
        int o = 1;
        o += (v > -1.9459101f);
        o += (v > -1.0986123f);
        o += (v > -0.51082563f);
        o += (v > -0x1.8p-23f);      // exact fp32 crossover of sigmoid==0.5
        o += (v >  0.51082563f);
        o += (v >  1.0986123f);
        o += (v >  1.9459101f);
        out[row * 8 + q + 4 * half] = (float)o;
    }
}

// ============================================================================
extern "C" void kernel_launch(void* const* d_in, const int* in_sizes, int n_in,
                              void* d_out, int out_size)
{
    const float* state = nullptr; const float* W1 = nullptr; const float* b1 = nullptr;
    const float* W2 = nullptr;    const float* b2 = nullptr; const float* W3 = nullptr;
    const float* b3 = nullptr;    const float* eps = nullptr;

    for (int pass = 0; pass < 2 && !state; ++pass) {
        long long mul = (pass == 0) ? 1 : 4;
        state = W1 = b1 = W2 = b2 = W3 = b3 = eps = nullptr;
        for (int i = 0; i < n_in; ++i) {
            const float* p = (const float*)d_in[i];
            long long sz = (long long)in_sizes[i];
            if      (sz == 33554432LL * mul) state = p;
            else if (sz == 32768LL    * mul) W1 = p;
            else if (sz == 65536LL    * mul) W2 = p;
            else if (sz == 4096LL     * mul) W3 = p;
            else if (sz == 2097152LL  * mul) eps = p;
            else if (sz == 16LL       * mul) b3 = p;
            else if (sz == 256LL      * mul) { if (!b1) b1 = p; else b2 = p; }
        }
    }
    if (!state || !W1 || !b1 || !W2 || !b2 || !W3 || !b3 || !eps) {
        state = (const float*)d_in[0]; W1 = (const float*)d_in[1];
        b1    = (const float*)d_in[2]; W2 = (const float*)d_in[3];
        b2    = (const float*)d_in[4]; W3 = (const float*)d_in[5];
        b3    = (const float*)d_in[6]; eps = (const float*)d_in[7];
    }

    static bool attr_done = false;
    if (!attr_done) {
        cudaFuncSetAttribute(actor_fused,
                             cudaFuncAttributeMaxDynamicSharedMemorySize, SMEM_TOTAL);
        attr_done = true;
    }

    prep_w<<<NBLK, 256>>>(W1, W2);
    actor_fused<<<NT, 256, SMEM_TOTAL>>>(state, b1, b2, W3, b3, eps, (float*)d_out);
}

// round 12
// speedup vs baseline: 1.5331x; 1.0078x over previous
#include <cuda_runtime.h>
#include <cstdint>
#include <cstddef>

#define B_ROWS 262144
#define TILE_R 64
#define NT     (B_ROWS / TILE_R)   // 4096 CTAs
#define PAD    260                 // buf row stride (floats)

#define NBLK1  16                  // layer-1 k8 blocks (K=128)
#define NBLK2  32                  // layer-2 k8 blocks (K=256)
#define NBLK   (NBLK1 + NBLK2)     // 48
#define TG_F4  258                 // float4 stride between tg rows (bank spread)
#define BLK_F4 (4 * TG_F4)         // 1032 float4 per block
#define BLK_BYTES (BLK_F4 * 16)    // 16512

// smem: buf[64*PAD] | Wf[2 slots * BLK_F4 float4] | 2 mbarriers
#define BUF_F      (TILE_R * PAD)          // 16640 floats
#define WF_F       (2 * BLK_F4 * 4)        // 8256 floats
#define MBAR_BYTE  ((BUF_F + WF_F) * 4)    // 99584 (8-aligned)
#define SMEM_TOTAL (MBAR_BYTE + 16)        // 99600 B

// Pre-split, fragment-packed weights (written by prep kernel):
// block bi, frag[tg][n] = {hi(k), hi(k+4), lo(k), lo(k+4)}, k = 8*bi_local + tg
__device__ __align__(16) float4 g_Wpk[NBLK * BLK_F4];

// ---------- tf32 split ----------
__device__ __forceinline__ void split_tf32(float x, uint32_t& hi, uint32_t& lo) {
    asm("cvt.rna.tf32.f32 %0, %1;" : "=r"(hi) : "f"(x));
    float r = x - __uint_as_float(hi);
    asm("cvt.rna.tf32.f32 %0, %1;" : "=r"(lo) : "f"(r));
}

// ---------- warp MMA m16n8k8 tf32 ----------
__device__ __forceinline__ void mma_tf32(float c[4], const uint32_t a[4],
                                         uint32_t b0, uint32_t b1) {
    asm volatile(
        "mma.sync.aligned.m16n8k8.row.col.f32.tf32.tf32.f32 "
        "{%0,%1,%2,%3},{%4,%5,%6,%7},{%8,%9},{%0,%1,%2,%3};"
        : "+f"(c[0]), "+f"(c[1]), "+f"(c[2]), "+f"(c[3])
        : "r"(a[0]), "r"(a[1]), "r"(a[2]), "r"(a[3]), "r"(b0), "r"(b1));
}

// ---------- mbarrier + 1D bulk copy ----------
__device__ __forceinline__ void mbar_init(uint32_t a, uint32_t cnt) {
    asm volatile("mbarrier.init.shared.b64 [%0], %1;" :: "r"(a), "r"(cnt) : "memory");
}
__device__ __forceinline__ void mbar_expect(uint32_t a, uint32_t bytes) {
    asm volatile("mbarrier.arrive.expect_tx.shared.b64 _, [%0], %1;" :: "r"(a), "r"(bytes) : "memory");
}
__device__ __forceinline__ void mbar_wait(uint32_t a, uint32_t parity) {
    asm volatile(
        "{\n\t.reg .pred P;\n"
        "W%=:\n\t"
        "mbarrier.try_wait.parity.acquire.cta.shared::cta.b64 P, [%0], %1, 0x989680;\n\t"
        "@P bra D%=;\n\t"
        "bra W%=;\n"
        "D%=:\n\t}"
        :: "r"(a), "r"(parity) : "memory");
}
__device__ __forceinline__ void bulk_g2s(uint32_t dst, const void* src,
                                         uint32_t bytes, uint32_t mbar) {
    asm volatile(
        "cp.async.bulk.shared::cta.global.mbarrier::complete_tx::bytes [%0], [%1], %2, [%3];"
        :: "r"(dst), "l"(src), "r"(bytes), "r"(mbar) : "memory");
}

// ============================================================================
// Prep kernel: split W into tf32 hi/lo, pack fragment-ready blocks.
// ============================================================================
__global__ void prep_w(const float* __restrict__ W1, const float* __restrict__ W2)
{
    const int bi = blockIdx.x;        // 0..47
    const int n  = threadIdx.x;       // 0..255
    const float* W = (bi < NBLK1) ? W1 : W2;
    const int K    = (bi < NBLK1) ? 128 : 256;
    const int kloc = (bi < NBLK1) ? bi * 8 : (bi - NBLK1) * 8;

    const float* src = W + (size_t)n * K + kloc;
    float e[8];
    *(float4*)&e[0] = *(const float4*)(src);
    *(float4*)&e[4] = *(const float4*)(src + 4);
    uint32_t hi[8], lo[8];
    #pragma unroll
    for (int i = 0; i < 8; ++i) split_tf32(e[i], hi[i], lo[i]);

    #pragma unroll
    for (int tg = 0; tg < 4; ++tg) {
        float4 f;
        f.x = __uint_as_float(hi[tg]);
        f.y = __uint_as_float(hi[tg + 4]);
        f.z = __uint_as_float(lo[tg]);
        f.w = __uint_as_float(lo[tg + 4]);
        g_Wpk[bi * BLK_F4 + tg * TG_F4 + n] = f;
    }
}

// ============================================================================
// Main fused kernel. Warp = 32 rows x 64 cols (2 m16 x 8 n8) — halves the
// redundant A-splitting vs the 64x32 layout (alu was 27.5%).
// ============================================================================
__global__ void __launch_bounds__(256, 2)
actor_fused(const float* __restrict__ state,
            const float* __restrict__ b1, const float* __restrict__ b2,
            const float* __restrict__ W3, const float* __restrict__ b3,
            const float* __restrict__ eps, float* __restrict__ out)
{
    extern __shared__ __align__(16) float smem[];
    float* buf     = smem;                 // [64][PAD]
    float* wfbase  = smem + BUF_F;         // 2 slots of BLK_F4 float4
    const uint32_t smem_u32 = (uint32_t)__cvta_generic_to_shared(smem);
    const uint32_t wf_u32   = smem_u32 + BUF_F * 4;
    const uint32_t mb[2]    = { smem_u32 + MBAR_BYTE, smem_u32 + MBAR_BYTE + 8 };

    const int tid  = threadIdx.x;
    const int t    = blockIdx.x;
    const int warp = tid >> 5;
    const int lane = tid & 31;
    const int wr0  = (warp & 1) * 32;     // warp row offset (2 groups of 32 rows)
    const int wc0  = (warp >> 1) * 64;    // warp col offset (4 groups of 64 cols)
    const int g    = lane >> 2;           // 0..7
    const int tg   = lane & 3;            // 0..3

    // init barriers + kick off first two weight blocks
    if (tid == 0) {
        mbar_init(mb[0], 1);
        mbar_init(mb[1], 1);
        asm volatile("fence.proxy.async.shared::cta;" ::: "memory");
        mbar_expect(mb[0], BLK_BYTES);
        bulk_g2s(wf_u32,             g_Wpk,          BLK_BYTES, mb[0]);
        mbar_expect(mb[1], BLK_BYTES);
        bulk_g2s(wf_u32 + BLK_BYTES, g_Wpk + BLK_F4, BLK_BYTES, mb[1]);
    }

    // load state tile [64][128] (overlaps with the bulk copies)
    {
        const float4* s4 = (const float4*)(state + (size_t)t * TILE_R * 128);
        #pragma unroll
        for (int j = 0; j < 8; ++j) {
            int idx = tid + j * 256;
            int r = idx >> 5, c4 = idx & 31;
            *(float4*)&buf[r * PAD + c4 * 4] = s4[idx];
        }
    }
    __syncthreads();   // state tile + barrier init visible

    // ---- two GEMM phases ----
    #pragma unroll 1
    for (int phase = 0; phase < 2; ++phase) {
        const int b0 = phase ? NBLK1 : 0;
        const int nb = phase ? NBLK2 : NBLK1;
        const float* bias = phase ? b2 : b1;

        float c[2][8][4];
        #pragma unroll
        for (int i = 0; i < 2; ++i)
            #pragma unroll
            for (int j = 0; j < 8; ++j)
                #pragma unroll
                for (int q = 0; q < 4; ++q) c[i][j][q] = 0.f;

        #pragma unroll 1
        for (int ib = 0; ib < nb; ++ib) {
            const int bi = b0 + ib;
            mbar_wait(mb[bi & 1], (bi >> 1) & 1);

            const float* Wf = wfbase + (size_t)(bi & 1) * BLK_F4 * 4;
            float4 Bf[8];
            #pragma unroll
            for (int j = 0; j < 8; ++j)
                Bf[j] = *(const float4*)&Wf[(tg * TG_F4 + wc0 + 8 * j + g) * 4];

            const int kb = ib * 8;
            // A fragments for the 2 m16 tiles of this warp's 32 rows
            uint32_t ahi[2][4], alo[2][4];
            #pragma unroll
            for (int i = 0; i < 2; ++i) {
                int r0 = wr0 + 16 * i + g;
                split_tf32(buf[r0 * PAD + kb + tg],           ahi[i][0], alo[i][0]);
                split_tf32(buf[(r0 + 8) * PAD + kb + tg],     ahi[i][1], alo[i][1]);
                split_tf32(buf[r0 * PAD + kb + tg + 4],       ahi[i][2], alo[i][2]);
                split_tf32(buf[(r0 + 8) * PAD + kb + tg + 4], ahi[i][3], alo[i][3]);
            }
            #pragma unroll
            for (int j = 0; j < 8; ++j) {
                uint32_t bh0 = __float_as_uint(Bf[j].x), bh1 = __float_as_uint(Bf[j].y);
                uint32_t bl0 = __float_as_uint(Bf[j].z), bl1 = __float_as_uint(Bf[j].w);
                #pragma unroll
                for (int i = 0; i < 2; ++i) {
                    mma_tf32(c[i][j], ahi[i], bh0, bh1);   // hi*hi
                    mma_tf32(c[i][j], alo[i], bh0, bh1);   // lo*hi
                    mma_tf32(c[i][j], ahi[i], bl0, bl1);   // hi*lo
                }
            }

            __syncthreads();   // all warps done with this slot (and prior buf reads)
            if (tid == 0 && bi + 2 < NBLK) {
                mbar_expect(mb[bi & 1], BLK_BYTES);
                bulk_g2s(wf_u32 + (uint32_t)(bi & 1) * BLK_BYTES,
                         g_Wpk + (size_t)(bi + 2) * BLK_F4, BLK_BYTES, mb[bi & 1]);
            }
        }

        // epilogue: bias + relu, in place (last iteration ended with sync)
        #pragma unroll
        for (int i = 0; i < 2; ++i) {
            int r0 = wr0 + 16 * i + g;
            #pragma unroll
            for (int j = 0; j < 8; ++j) {
                int col = wc0 + 8 * j + 2 * tg;
                float2 bb = *(const float2*)(bias + col);
                float v0 = fmaxf(c[i][j][0] + bb.x, 0.f);
                float v1 = fmaxf(c[i][j][1] + bb.y, 0.f);
                float v2 = fmaxf(c[i][j][2] + bb.x, 0.f);
                float v3 = fmaxf(c[i][j][3] + bb.y, 0.f);
                *(float2*)&buf[r0 * PAD + col]       = make_float2(v0, v1);
                *(float2*)&buf[(r0 + 8) * PAD + col] = make_float2(v2, v3);
            }
        }
        __syncthreads();   // updated buf visible before next phase / head
    }

    // ================= head (exact fp32 scalar) =================
    float* Ws = wfbase;   // 16*260 = 4160 floats, fits in slot area
    #pragma unroll
    for (int j = 0; j < 4; ++j) {
        int idx = tid + j * 256;              // 16 rows x 64 float4
        int jr = idx >> 6, k4 = idx & 63;
        *(float4*)&Ws[jr * 260 + k4 * 4] = *(const float4*)(W3 + (size_t)jr * 256 + k4 * 4);
    }
    __syncthreads();

    const int r = tid >> 2;
    const int q = tid & 3;

    float d[4] = {0.f, 0.f, 0.f, 0.f};
    #pragma unroll 8
    for (int k4 = 0; k4 < 64; ++k4) {
        float4 h = *(const float4*)&buf[r * PAD + k4 * 4];
        #pragma unroll
        for (int cidx = 0; cidx < 4; ++cidx) {
            int jj = q + 4 * cidx;
            float4 w = *(const float4*)&Ws[jj * 260 + k4 * 4];
            d[cidx] = fmaf(h.x, w.x, d[cidx]);
            d[cidx] = fmaf(h.y, w.y, d[cidx]);
            d[cidx] = fmaf(h.z, w.z, d[cidx]);
            d[cidx] = fmaf(h.w, w.w, d[cidx]);
        }
    }

    const size_t row = (size_t)t * TILE_R + r;
    float u0 = d[0] + b3[q];
    float u1 = d[1] + b3[q + 4];
    float s0 = fabsf(d[2] + b3[q + 8]);
    float s1 = fabsf(d[3] + b3[q + 12]);
    float e0 = eps[row * 8 + q];
    float e1 = eps[row * 8 + q + 4];
    float v0 = fmaf(s0, e0, u0);
    float v1 = fmaf(s1, e1, u1);

    #pragma unroll
    for (int half = 0; half < 2; ++half) {
        float v = half ? v1 : v0;
        int o = 1;
        o += (v > -1.9459101f);
        o += (v > -1.0986123f);
        o += (v > -0.51082563f);
        o += (v > -0x1.8p-23f);      // exact fp32 crossover of sigmoid==0.5
        o += (v >  0.51082563f);
        o += (v >  1.0986123f);
        o += (v >  1.9459101f);
        out[row * 8 + q + 4 * half] = (float)o;
    }
}

// ============================================================================
extern "C" void kernel_launch(void* const* d_in, const int* in_sizes, int n_in,
                              void* d_out, int out_size)
{
    const float* state = nullptr; const float* W1 = nullptr; const float* b1 = nullptr;
    const float* W2 = nullptr;    const float* b2 = nullptr; const float* W3 = nullptr;
    const float* b3 = nullptr;    const float* eps = nullptr;

    for (int pass = 0; pass < 2 && !state; ++pass) {
        long long mul = (pass == 0) ? 1 : 4;
        state = W1 = b1 = W2 = b2 = W3 = b3 = eps = nullptr;
        for (int i = 0; i < n_in; ++i) {
            const float* p = (const float*)d_in[i];
            long long sz = (long long)in_sizes[i];
            if      (sz == 33554432LL * mul) state = p;
            else if (sz == 32768LL    * mul) W1 = p;
            else if (sz == 65536LL    * mul) W2 = p;
            else if (sz == 4096LL     * mul) W3 = p;
            else if (sz == 2097152LL  * mul) eps = p;
            else if (sz == 16LL       * mul) b3 = p;
            else if (sz == 256LL      * mul) { if (!b1) b1 = p; else b2 = p; }
        }
    }
    if (!state || !W1 || !b1 || !W2 || !b2 || !W3 || !b3 || !eps) {
        state = (const float*)d_in[0]; W1 = (const float*)d_in[1];
        b1    = (const float*)d_in[2]; W2 = (const float*)d_in[3];
        b2    = (const float*)d_in[4]; W3 = (const float*)d_in[5];
        b3    = (const float*)d_in[6]; eps = (const float*)d_in[7];
    }

    static bool attr_done = false;
    if (!attr_done) {
        cudaFuncSetAttribute(actor_fused,
                             cudaFuncAttributeMaxDynamicSharedMemorySize, SMEM_TOTAL);
        attr_done = true;
    }

    prep_w<<<NBLK, 256>>>(W1, W2);
    actor_fused<<<NT, 256, SMEM_TOTAL>>>(state, b1, b2, W3, b3, eps, (float*)d_out);
}

// round 14
// speedup vs baseline: 1.6197x; 1.0565x over previous
#include <cuda_runtime.h>
#include <cstdint>
#include <cstddef>

#define B_ROWS 262144
#define TILE_R 64
#define NT     (B_ROWS / TILE_R)   // 4096 CTAs
#define PAD    260                 // buf row stride (floats)

#define NBLK1  16                  // layer-1 k8 blocks (K=128)
#define NBLK2  32                  // layer-2 k8 blocks (K=256)
#define NBLK   (NBLK1 + NBLK2)     // 48
#define TG_F4  258                 // float4 stride between tg rows (bank spread)
#define BLK_F4 (4 * TG_F4)         // 1032 float4 per block
#define BLK_BYTES (BLK_F4 * 16)    // 16512

// smem: buf[64*PAD] | Wf[2 slots * BLK_F4 float4] | 4 mbarriers (2 full + 2 empty)
#define BUF_F      (TILE_R * PAD)          // 16640 floats
#define WF_F       (2 * BLK_F4 * 4)        // 8256 floats
#define MBAR_BYTE  ((BUF_F + WF_F) * 4)    // 99584 (8-aligned)
#define SMEM_TOTAL (MBAR_BYTE + 32)        // 99616 B

// Pre-split, fragment-packed weights (written by prep kernel):
// block bi, frag[tg][n] = {hi(k), hi(k+4), lo(k), lo(k+4)}, k = 8*bi_local + tg
__device__ __align__(16) float4 g_Wpk[NBLK * BLK_F4];

// ---------- tf32 split ----------
__device__ __forceinline__ void split_tf32(float x, uint32_t& hi, uint32_t& lo) {
    asm("cvt.rna.tf32.f32 %0, %1;" : "=r"(hi) : "f"(x));
    float r = x - __uint_as_float(hi);
    asm("cvt.rna.tf32.f32 %0, %1;" : "=r"(lo) : "f"(r));
}

// ---------- warp MMA m16n8k8 tf32 ----------
__device__ __forceinline__ void mma_tf32(float c[4], const uint32_t a[4],
                                         uint32_t b0, uint32_t b1) {
    asm volatile(
        "mma.sync.aligned.m16n8k8.row.col.f32.tf32.tf32.f32 "
        "{%0,%1,%2,%3},{%4,%5,%6,%7},{%8,%9},{%0,%1,%2,%3};"
        : "+f"(c[0]), "+f"(c[1]), "+f"(c[2]), "+f"(c[3])
        : "r"(a[0]), "r"(a[1]), "r"(a[2]), "r"(a[3]), "r"(b0), "r"(b1));
}

// ---------- mbarrier helpers ----------
__device__ __forceinline__ void mbar_init(uint32_t a, uint32_t cnt) {
    asm volatile("mbarrier.init.shared.b64 [%0], %1;" :: "r"(a), "r"(cnt) : "memory");
}
__device__ __forceinline__ void mbar_expect(uint32_t a, uint32_t bytes) {
    asm volatile("mbarrier.arrive.expect_tx.shared.b64 _, [%0], %1;" :: "r"(a), "r"(bytes) : "memory");
}
__device__ __forceinline__ void mbar_arrive(uint32_t a) {
    asm volatile("mbarrier.arrive.release.cta.shared::cta.b64 _, [%0];" :: "r"(a) : "memory");
}
__device__ __forceinline__ void mbar_wait(uint32_t a, uint32_t parity) {
    asm volatile(
        "{\n\t.reg .pred P;\n"
        "W%=:\n\t"
        "mbarrier.try_wait.parity.acquire.cta.shared::cta.b64 P, [%0], %1, 0x989680;\n\t"
        "@P bra D%=;\n\t"
        "bra W%=;\n"
        "D%=:\n\t}"
        :: "r"(a), "r"(parity) : "memory");
}
__device__ __forceinline__ void bulk_g2s(uint32_t dst, const void* src,
                                         uint32_t bytes, uint32_t mbar) {
    asm volatile(
        "cp.async.bulk.shared::cta.global.mbarrier::complete_tx::bytes [%0], [%1], %2, [%3];"
        :: "r"(dst), "l"(src), "r"(bytes), "r"(mbar) : "memory");
}

// ============================================================================
// Prep kernel: split W into tf32 hi/lo, pack fragment-ready blocks.
// ============================================================================
__global__ void prep_w(const float* __restrict__ W1, const float* __restrict__ W2)
{
    const int bi = blockIdx.x;        // 0..47
    const int n  = threadIdx.x;       // 0..255
    const float* W = (bi < NBLK1) ? W1 : W2;
    const int K    = (bi < NBLK1) ? 128 : 256;
    const int kloc = (bi < NBLK1) ? bi * 8 : (bi - NBLK1) * 8;

    const float* src = W + (size_t)n * K + kloc;
    float e[8];
    *(float4*)&e[0] = *(const float4*)(src);
    *(float4*)&e[4] = *(const float4*)(src + 4);
    uint32_t hi[8], lo[8];
    #pragma unroll
    for (int i = 0; i < 8; ++i) split_tf32(e[i], hi[i], lo[i]);

    #pragma unroll
    for (int tg = 0; tg < 4; ++tg) {
        float4 f;
        f.x = __uint_as_float(hi[tg]);
        f.y = __uint_as_float(hi[tg + 4]);
        f.z = __uint_as_float(lo[tg]);
        f.w = __uint_as_float(lo[tg + 4]);
        g_Wpk[bi * BLK_F4 + tg * TG_F4 + n] = f;
    }
}

// ============================================================================
// Main fused kernel. Warp = 32 rows x 64 cols (2 m16 x 8 n8).
// Decoupled producer/consumer ring: full[s] = tx barrier from cp.async.bulk;
// empty[s] = 8-warp arrive barrier. The empty-arrive is issued ONLY AFTER the
// MMAs that consume the Bf registers — the MMA register dependency guarantees
// the slot LDS has been serviced before the arrive (fixes the R13 race).
// ============================================================================
__global__ void __launch_bounds__(256, 2)
actor_fused(const float* __restrict__ state,
            const float* __restrict__ b1, const float* __restrict__ b2,
            const float* __restrict__ W3, const float* __restrict__ b3,
            const float* __restrict__ eps, float* __restrict__ out)
{
    extern __shared__ __align__(16) float smem[];
    float* buf     = smem;                 // [64][PAD]
    float* wfbase  = smem + BUF_F;         // 2 slots of BLK_F4 float4
    const uint32_t smem_u32 = (uint32_t)__cvta_generic_to_shared(smem);
    const uint32_t wf_u32   = smem_u32 + BUF_F * 4;
    const uint32_t mbf[2]   = { smem_u32 + MBAR_BYTE,      smem_u32 + MBAR_BYTE + 8 };
    const uint32_t mbe[2]   = { smem_u32 + MBAR_BYTE + 16, smem_u32 + MBAR_BYTE + 24 };

    const int tid  = threadIdx.x;
    const int t    = blockIdx.x;
    const int warp = tid >> 5;
    const int lane = tid & 31;
    const int wr0  = (warp & 1) * 32;     // warp row offset (2 groups of 32 rows)
    const int wc0  = (warp >> 1) * 64;    // warp col offset (4 groups of 64 cols)
    const int g    = lane >> 2;           // 0..7
    const int tg   = lane & 3;            // 0..3

    // init barriers + kick off first two weight blocks
    if (tid == 0) {
        mbar_init(mbf[0], 1);
        mbar_init(mbf[1], 1);
        mbar_init(mbe[0], 8);
        mbar_init(mbe[1], 8);
        asm volatile("fence.proxy.async.shared::cta;" ::: "memory");
        mbar_expect(mbf[0], BLK_BYTES);
        bulk_g2s(wf_u32,             g_Wpk,          BLK_BYTES, mbf[0]);
        mbar_expect(mbf[1], BLK_BYTES);
        bulk_g2s(wf_u32 + BLK_BYTES, g_Wpk + BLK_F4, BLK_BYTES, mbf[1]);
    }

    // load state tile [64][128] (overlaps with the bulk copies)
    {
        const float4* s4 = (const float4*)(state + (size_t)t * TILE_R * 128);
        #pragma unroll
        for (int j = 0; j < 8; ++j) {
            int idx = tid + j * 256;
            int r = idx >> 5, c4 = idx & 31;
            *(float4*)&buf[r * PAD + c4 * 4] = s4[idx];
        }
    }
    __syncthreads();   // state tile + barrier init visible to all warps

    // ---- two GEMM phases ----
    #pragma unroll 1
    for (int phase = 0; phase < 2; ++phase) {
        const int b0 = phase ? NBLK1 : 0;
        const int nb = phase ? NBLK2 : NBLK1;
        const float* bias = phase ? b2 : b1;

        float c[2][8][4];
        #pragma unroll
        for (int i = 0; i < 2; ++i)
            #pragma unroll
            for (int j = 0; j < 8; ++j)
                #pragma unroll
                for (int q = 0; q < 4; ++q) c[i][j][q] = 0.f;

        #pragma unroll 1
        for (int ib = 0; ib < nb; ++ib) {
            const int bi = b0 + ib;
            const int s  = bi & 1;
            const uint32_t par = (uint32_t)((bi >> 1) & 1);

            mbar_wait(mbf[s], par);   // slot filled?

            const float* Wf = wfbase + (size_t)s * BLK_F4 * 4;
            float4 Bf[8];
            #pragma unroll
            for (int j = 0; j < 8; ++j)
                Bf[j] = *(const float4*)&Wf[(tg * TG_F4 + wc0 + 8 * j + g) * 4];

            const int kb = ib * 8;
            uint32_t ahi[2][4], alo[2][4];
            #pragma unroll
            for (int i = 0; i < 2; ++i) {
                int r0 = wr0 + 16 * i + g;
                split_tf32(buf[r0 * PAD + kb + tg],           ahi[i][0], alo[i][0]);
                split_tf32(buf[(r0 + 8) * PAD + kb + tg],     ahi[i][1], alo[i][1]);
                split_tf32(buf[r0 * PAD + kb + tg + 4],       ahi[i][2], alo[i][2]);
                split_tf32(buf[(r0 + 8) * PAD + kb + tg + 4], ahi[i][3], alo[i][3]);
            }
            #pragma unroll
            for (int j = 0; j < 8; ++j) {
                uint32_t bh0 = __float_as_uint(Bf[j].x), bh1 = __float_as_uint(Bf[j].y);
                uint32_t bl0 = __float_as_uint(Bf[j].z), bl1 = __float_as_uint(Bf[j].w);
                #pragma unroll
                for (int i = 0; i < 2; ++i) {
                    mma_tf32(c[i][j], ahi[i], bh0, bh1);   // hi*hi
                    mma_tf32(c[i][j], alo[i], bh0, bh1);   // lo*hi
                    mma_tf32(c[i][j], ahi[i], bl0, bl1);   // hi*lo
                }
            }

            // AFTER the MMAs consumed Bf (register scoreboard => LDS serviced):
            // this warp is provably done reading the slot.
            if (lane == 0) mbar_arrive(mbe[s]);

            // producer: once all 8 warps drained the slot, refill it
            if (warp == 0 && bi + 2 < NBLK) {
                mbar_wait(mbe[s], par);
                if (lane == 0) {
                    mbar_expect(mbf[s], BLK_BYTES);
                    bulk_g2s(wf_u32 + (uint32_t)s * BLK_BYTES,
                             g_Wpk + (size_t)(bi + 2) * BLK_F4, BLK_BYTES, mbf[s]);
                }
            }
        }

        __syncthreads();   // all warps done reading buf before in-place overwrite
        #pragma unroll
        for (int i = 0; i < 2; ++i) {
            int r0 = wr0 + 16 * i + g;
            #pragma unroll
            for (int j = 0; j < 8; ++j) {
                int col = wc0 + 8 * j + 2 * tg;
                float2 bb = *(const float2*)(bias + col);
                float v0 = fmaxf(c[i][j][0] + bb.x, 0.f);
                float v1 = fmaxf(c[i][j][1] + bb.y, 0.f);
                float v2 = fmaxf(c[i][j][2] + bb.x, 0.f);
                float v3 = fmaxf(c[i][j][3] + bb.y, 0.f);
                *(float2*)&buf[r0 * PAD + col]       = make_float2(v0, v1);
                *(float2*)&buf[(r0 + 8) * PAD + col] = make_float2(v2, v3);
            }
        }
        __syncthreads();   // updated buf visible before next phase / head
    }

    // ================= head (exact fp32 scalar) =================
    float* Ws = wfbase;   // 16*260 = 4160 floats, fits in slot area
    #pragma unroll
    for (int j = 0; j < 4; ++j) {
        int idx = tid + j * 256;              // 16 rows x 64 float4
        int jr = idx >> 6, k4 = idx & 63;
        *(float4*)&Ws[jr * 260 + k4 * 4] = *(const float4*)(W3 + (size_t)jr * 256 + k4 * 4);
    }
    __syncthreads();

    const int r = tid >> 2;
    const int q = tid & 3;

    float d[4] = {0.f, 0.f, 0.f, 0.f};
    #pragma unroll 8
    for (int k4 = 0; k4 < 64; ++k4) {
        float4 h = *(const float4*)&buf[r * PAD + k4 * 4];
        #pragma unroll
        for (int cidx = 0; cidx < 4; ++cidx) {
            int jj = q + 4 * cidx;
            float4 w = *(const float4*)&Ws[jj * 260 + k4 * 4];
            d[cidx] = fmaf(h.x, w.x, d[cidx]);
            d[cidx] = fmaf(h.y, w.y, d[cidx]);
            d[cidx] = fmaf(h.z, w.z, d[cidx]);
            d[cidx] = fmaf(h.w, w.w, d[cidx]);
        }
    }

    const size_t row = (size_t)t * TILE_R + r;
    float u0 = d[0] + b3[q];
    float u1 = d[1] + b3[q + 4];
    float s0 = fabsf(d[2] + b3[q + 8]);
    float s1 = fabsf(d[3] + b3[q + 12]);
    float e0 = eps[row * 8 + q];
    float e1 = eps[row * 8 + q + 4];
    float v0 = fmaf(s0, e0, u0);
    float v1 = fmaf(s1, e1, u1);

    #pragma unroll
    for (int half = 0; half < 2; ++half) {
        float v = half ? v1 : v0;
        int o = 1;
        o += (v > -1.9459101f);
        o += (v > -1.0986123f);
        o += (v > -0.51082563f);
        o += (v > -0x1.8p-23f);      // exact fp32 crossover of sigmoid==0.5
        o += (v >  0.51082563f);
        o += (v >  1.0986123f);
        o += (v >  1.9459101f);
        out[row * 8 + q + 4 * half] = (float)o;
    }
}

// ============================================================================
extern "C" void kernel_launch(void* const* d_in, const int* in_sizes, int n_in,
                              void* d_out, int out_size)
{
    const float* state = nullptr; const float* W1 = nullptr; const float* b1 = nullptr;
    const float* W2 = nullptr;    const float* b2 = nullptr; const float* W3 = nullptr;
    const float* b3 = nullptr;    const float* eps = nullptr;

    for (int pass = 0; pass < 2 && !state; ++pass) {
        long long mul = (pass == 0) ? 1 : 4;
        state = W1 = b1 = W2 = b2 = W3 = b3 = eps = nullptr;
        for (int i = 0; i < n_in; ++i) {
            const float* p = (const float*)d_in[i];
            long long sz = (long long)in_sizes[i];
            if      (sz == 33554432LL * mul) state = p;
            else if (sz == 32768LL    * mul) W1 = p;
            else if (sz == 65536LL    * mul) W2 = p;
            else if (sz == 4096LL     * mul) W3 = p;
            else if (sz == 2097152LL  * mul) eps = p;
            else if (sz == 16LL       * mul) b3 = p;
            else if (sz == 256LL      * mul) { if (!b1) b1 = p; else b2 = p; }
        }
    }
    if (!state || !W1 || !b1 || !W2 || !b2 || !W3 || !b3 || !eps) {
        state = (const float*)d_in[0]; W1 = (const float*)d_in[1];
        b1    = (const float*)d_in[2]; W2 = (const float*)d_in[3];
        b2    = (const float*)d_in[4]; W3 = (const float*)d_in[5];
        b3    = (const float*)d_in[6]; eps = (const float*)d_in[7];
    }

    static bool attr_done = false;
    if (!attr_done) {
        cudaFuncSetAttribute(actor_fused,
                             cudaFuncAttributeMaxDynamicSharedMemorySize, SMEM_TOTAL);
        attr_done = true;
    }

    prep_w<<<NBLK, 256>>>(W1, W2);
    actor_fused<<<NT, 256, SMEM_TOTAL>>>(state, b1, b2, W3, b3, eps, (float*)d_out);
}

// round 17
// speedup vs baseline: 2.3759x; 1.4669x over previous
#include <cuda_runtime.h>
#include <cstdint>
#include <cstddef>

#define B_ROWS 262144
#define TILE_R 64
#define NT     (B_ROWS / TILE_R)   // 4096 CTAs
#define PAD    260                 // buf row stride (floats)

#define NBLK1  8                   // layer-1 k16 blocks (K=128)
#define NBLK2  16                  // layer-2 k16 blocks (K=256)
#define NBLK   (NBLK1 + NBLK2)     // 24
#define NSTR   264                 // u32 stride per (s,q,tg) row: 264 % 32 == 8 -> conflict-free
#define BLK_U32 (16 * NSTR)        // 4224 u32 per block (2 streams x 2 q x 4 tg x 264)
#define BLK_BYTES (BLK_U32 * 4)    // 16896

// smem: buf[64*PAD] f32 | ring[2 * BLK_U32] u32 | 4 mbarriers
#define BUF_F      (TILE_R * PAD)              // 16640 floats
#define RING_BYTE  (BUF_F * 4)                 // 66560
#define MBAR_BYTE  (RING_BYTE + 2 * BLK_BYTES) // 100352 (8-aligned)
#define SMEM_TOTAL (MBAR_BYTE + 32)            // 100384 B  (2 CTAs/SM)

// Pre-split bf16 2-term weights, fragment-packed (written by prep kernel):
// g_Wpk[bi*BLK_U32 + (s*8 + q*4 + tg)*NSTR + n] =
//   bf16(w[n][kb+2tg+8q], term s) | bf16(w[n][kb+2tg+1+8q], term s) << 16
__device__ __align__(16) uint32_t g_Wpk[NBLK * BLK_U32];

// ---------- bf16 2-term split ----------
__device__ __forceinline__ void split_bf16(float v, unsigned short& h0, unsigned short& h1) {
    asm("cvt.rn.bf16.f32 %0, %1;" : "=h"(h0) : "f"(v));
    float f0 = __uint_as_float((unsigned)h0 << 16);   // exact bf16 -> f32
    float r  = v - f0;                                // exact
    asm("cvt.rn.bf16.f32 %0, %1;" : "=h"(h1) : "f"(r));
}
__device__ __forceinline__ void split2(float x, float y, uint32_t& hi, uint32_t& lo) {
    unsigned short x0, x1, y0, y1;
    split_bf16(x, x0, x1);
    split_bf16(y, y0, y1);
    hi = (uint32_t)x0 | ((uint32_t)y0 << 16);
    lo = (uint32_t)x1 | ((uint32_t)y1 << 16);
}

// ---------- warp MMA m16n8k16 bf16 ----------
__device__ __forceinline__ void mma_bf16(float c[4], const uint32_t a[4],
                                         uint32_t b0, uint32_t b1) {
    asm volatile(
        "mma.sync.aligned.m16n8k16.row.col.f32.bf16.bf16.f32 "
        "{%0,%1,%2,%3},{%4,%5,%6,%7},{%8,%9},{%0,%1,%2,%3};"
        : "+f"(c[0]), "+f"(c[1]), "+f"(c[2]), "+f"(c[3])
        : "r"(a[0]), "r"(a[1]), "r"(a[2]), "r"(a[3]), "r"(b0), "r"(b1));
}

// ---------- mbarrier helpers (proven in R14) ----------
__device__ __forceinline__ void mbar_init(uint32_t a, uint32_t cnt) {
    asm volatile("mbarrier.init.shared.b64 [%0], %1;" :: "r"(a), "r"(cnt) : "memory");
}
__device__ __forceinline__ void mbar_expect(uint32_t a, uint32_t bytes) {
    asm volatile("mbarrier.arrive.expect_tx.shared.b64 _, [%0], %1;" :: "r"(a), "r"(bytes) : "memory");
}
__device__ __forceinline__ void mbar_arrive(uint32_t a) {
    asm volatile("mbarrier.arrive.release.cta.shared::cta.b64 _, [%0];" :: "r"(a) : "memory");
}
__device__ __forceinline__ void mbar_wait(uint32_t a, uint32_t parity) {
    asm volatile(
        "{\n\t.reg .pred P;\n"
        "W%=:\n\t"
        "mbarrier.try_wait.parity.acquire.cta.shared::cta.b64 P, [%0], %1, 0x989680;\n\t"
        "@P bra D%=;\n\tbra W%=;\nD%=:\n\t}"
        :: "r"(a), "r"(parity) : "memory");
}
__device__ __forceinline__ void bulk_g2s(uint32_t dst, const void* src,
                                         uint32_t bytes, uint32_t mbar) {
    asm volatile(
        "cp.async.bulk.shared::cta.global.mbarrier::complete_tx::bytes [%0], [%1], %2, [%3];"
        :: "r"(dst), "l"(src), "r"(bytes), "r"(mbar) : "memory");
}

// ============================================================================
// Prep kernel: bf16 2-term split + fragment packing. 24 blocks x 256 threads.
// blk 0..7:  W1 (K=128), kb = blk*16
// blk 8..23: W2 (K=256), kb = (blk-8)*16
// ============================================================================
__global__ void prep_w(const float* __restrict__ W1, const float* __restrict__ W2)
{
    const int blk = blockIdx.x;
    const int n   = threadIdx.x;
    const float* W; int K, kb;
    if (blk < NBLK1) { W = W1; K = 128; kb = blk * 16; }
    else             { W = W2; K = 256; kb = (blk - NBLK1) * 16; }

    const float4* src = (const float4*)(W + (size_t)n * K + kb);
    float w[16];
    #pragma unroll
    for (int f = 0; f < 4; ++f) *(float4*)&w[f * 4] = src[f];

    unsigned short h0[16], h1[16];
    #pragma unroll
    for (int k = 0; k < 16; ++k) split_bf16(w[k], h0[k], h1[k]);

    uint32_t* dst = g_Wpk + (size_t)blk * BLK_U32;
    #pragma unroll
    for (int q = 0; q < 2; ++q)
        #pragma unroll
        for (int tg = 0; tg < 4; ++tg) {
            int k0 = 2 * tg + 8 * q;
            dst[(0 * 8 + q * 4 + tg) * NSTR + n] = (uint32_t)h0[k0] | ((uint32_t)h0[k0 + 1] << 16);
            dst[(1 * 8 + q * 4 + tg) * NSTR + n] = (uint32_t)h1[k0] | ((uint32_t)h1[k0 + 1] << 16);
        }
}

// ============================================================================
// Main fused kernel. Warp = 32 rows x 64 cols (2 m16 x 8 n8), bf16 3-stream.
// Ring: full[s] = tx barrier; empty[s] = 8-warp arrive AFTER the MMAs (R14 fix).
// ============================================================================
__global__ void __launch_bounds__(256, 2)
actor_fused(const float* __restrict__ state,
            const float* __restrict__ b1, const float* __restrict__ b2,
            const float* __restrict__ W3, const float* __restrict__ b3,
            const float* __restrict__ eps, float* __restrict__ out)
{
    extern __shared__ __align__(16) float smem[];
    float*    buf  = smem;                              // [64][PAD]
    uint32_t* ring = (uint32_t*)((char*)smem + RING_BYTE);
    const uint32_t smem_u32 = (uint32_t)__cvta_generic_to_shared(smem);
    const uint32_t ring_u32 = smem_u32 + RING_BYTE;
    const uint32_t mbf[2]   = { smem_u32 + MBAR_BYTE,      smem_u32 + MBAR_BYTE + 8 };
    const uint32_t mbe[2]   = { smem_u32 + MBAR_BYTE + 16, smem_u32 + MBAR_BYTE + 24 };

    const int tid  = threadIdx.x;
    const int t    = blockIdx.x;
    const int warp = tid >> 5;
    const int lane = tid & 31;
    const int wr0  = (warp & 1) * 32;     // warp row offset
    const int wc0  = (warp >> 1) * 64;    // warp col offset
    const int g    = lane >> 2;           // 0..7
    const int tg   = lane & 3;            // 0..3

    if (tid == 0) {
        mbar_init(mbf[0], 1);
        mbar_init(mbf[1], 1);
        mbar_init(mbe[0], 8);
        mbar_init(mbe[1], 8);
        asm volatile("fence.proxy.async.shared::cta;" ::: "memory");
        mbar_expect(mbf[0], BLK_BYTES);
        bulk_g2s(ring_u32,             g_Wpk,           BLK_BYTES, mbf[0]);
        mbar_expect(mbf[1], BLK_BYTES);
        bulk_g2s(ring_u32 + BLK_BYTES, g_Wpk + BLK_U32, BLK_BYTES, mbf[1]);
    }

    // load state tile [64][128]
    {
        const float4* s4 = (const float4*)(state + (size_t)t * TILE_R * 128);
        #pragma unroll
        for (int j = 0; j < 8; ++j) {
            int idx = tid + j * 256;
            int r = idx >> 5, c4 = idx & 31;
            *(float4*)&buf[r * PAD + c4 * 4] = s4[idx];
        }
    }
    __syncthreads();

    // ---- two GEMM phases ----
    #pragma unroll 1
    for (int phase = 0; phase < 2; ++phase) {
        const int b0 = phase ? NBLK1 : 0;
        const int nb = phase ? NBLK2 : NBLK1;
        const float* bias = phase ? b2 : b1;

        float c[2][8][4];
        #pragma unroll
        for (int i = 0; i < 2; ++i)
            #pragma unroll
            for (int j = 0; j < 8; ++j)
                #pragma unroll
                for (int q = 0; q < 4; ++q) c[i][j][q] = 0.f;

        #pragma unroll 1
        for (int ib = 0; ib < nb; ++ib) {
            const int bi = b0 + ib;
            const int s  = bi & 1;
            const uint32_t par = (uint32_t)((bi >> 1) & 1);

            mbar_wait(mbf[s], par);

            const uint32_t* Wf = ring + (size_t)s * BLK_U32;
            const int kb = ib * 16;

            // A fragments: 2 m16 tiles, bf16 2-term split from fp32 buf
            uint32_t ahi[2][4], alo[2][4];
            #pragma unroll
            for (int i = 0; i < 2; ++i) {
                const float* bp  = buf + (size_t)(wr0 + 16 * i + g) * PAD + kb;
                const float* bp8 = bp + 8 * PAD;
                float2 p00 = *(const float2*)(bp  + 2 * tg);
                float2 p10 = *(const float2*)(bp8 + 2 * tg);
                float2 p01 = *(const float2*)(bp  + 2 * tg + 8);
                float2 p11 = *(const float2*)(bp8 + 2 * tg + 8);
                split2(p00.x, p00.y, ahi[i][0], alo[i][0]);
                split2(p10.x, p10.y, ahi[i][1], alo[i][1]);
                split2(p01.x, p01.y, ahi[i][2], alo[i][2]);
                split2(p11.x, p11.y, ahi[i][3], alo[i][3]);
            }

            #pragma unroll
            for (int j = 0; j < 8; ++j) {
                const int n = wc0 + 8 * j + g;
                uint32_t bh0 = Wf[(0 + tg) * NSTR + n];        // s=0, q=0
                uint32_t bh1 = Wf[(4 + tg) * NSTR + n];        // s=0, q=1
                uint32_t bl0 = Wf[(8 + tg) * NSTR + n];        // s=1, q=0
                uint32_t bl1 = Wf[(12 + tg) * NSTR + n];       // s=1, q=1
                #pragma unroll
                for (int i = 0; i < 2; ++i) {
                    mma_bf16(c[i][j], ahi[i], bh0, bh1);   // a0*b0
                    mma_bf16(c[i][j], alo[i], bh0, bh1);   // a1*b0
                    mma_bf16(c[i][j], ahi[i], bl0, bl1);   // a0*b1
                }
            }

            // after MMAs consumed the B regs (LDS provably serviced)
            if (lane == 0) mbar_arrive(mbe[s]);

            if (warp == 0 && bi + 2 < NBLK) {
                mbar_wait(mbe[s], par);
                if (lane == 0) {
                    mbar_expect(mbf[s], BLK_BYTES);
                    bulk_g2s(ring_u32 + (uint32_t)s * BLK_BYTES,
                             g_Wpk + (size_t)(bi + 2) * BLK_U32, BLK_BYTES, mbf[s]);
                }
            }
        }

        __syncthreads();   // all warps done reading buf before in-place overwrite
        #pragma unroll
        for (int i = 0; i < 2; ++i) {
            int r0 = wr0 + 16 * i + g;
            #pragma unroll
            for (int j = 0; j < 8; ++j) {
                int col = wc0 + 8 * j + 2 * tg;
                float2 bb = *(const float2*)(bias + col);
                float v0 = fmaxf(c[i][j][0] + bb.x, 0.f);
                float v1 = fmaxf(c[i][j][1] + bb.y, 0.f);
                float v2 = fmaxf(c[i][j][2] + bb.x, 0.f);
                float v3 = fmaxf(c[i][j][3] + bb.y, 0.f);
                *(float2*)&buf[r0 * PAD + col]       = make_float2(v0, v1);
                *(float2*)&buf[(r0 + 8) * PAD + col] = make_float2(v2, v3);
            }
        }
        __syncthreads();   // updated buf visible before next phase / head
    }

    // ================= head (exact fp32 scalar, proven) =================
    float* Ws = (float*)ring;   // 16*260 floats = 16640 B <= 2*BLK_BYTES
    #pragma unroll
    for (int j = 0; j < 4; ++j) {
        int idx = tid + j * 256;              // 16 rows x 64 float4
        int jr = idx >> 6, k4 = idx & 63;
        *(float4*)&Ws[jr * 260 + k4 * 4] = *(const float4*)(W3 + (size_t)jr * 256 + k4 * 4);
    }
    __syncthreads();

    const int r = tid >> 2;
    const int q = tid & 3;

    float d[4] = {0.f, 0.f, 0.f, 0.f};
    #pragma unroll 8
    for (int k4 = 0; k4 < 64; ++k4) {
        float4 h = *(const float4*)&buf[r * PAD + k4 * 4];
        #pragma unroll
        for (int cidx = 0; cidx < 4; ++cidx) {
            int jj = q + 4 * cidx;
            float4 w = *(const float4*)&Ws[jj * 260 + k4 * 4];
            d[cidx] = fmaf(h.x, w.x, d[cidx]);
            d[cidx] = fmaf(h.y, w.y, d[cidx]);
            d[cidx] = fmaf(h.z, w.z, d[cidx]);
            d[cidx] = fmaf(h.w, w.w, d[cidx]);
        }
    }

    const size_t row = (size_t)t * TILE_R + r;
    float u0 = d[0] + b3[q];
    float u1 = d[1] + b3[q + 4];
    float s0 = fabsf(d[2] + b3[q + 8]);
    float s1 = fabsf(d[3] + b3[q + 12]);
    float e0 = eps[row * 8 + q];
    float e1 = eps[row * 8 + q + 4];
    float v0 = fmaf(s0, e0, u0);
    float v1 = fmaf(s1, e1, u1);

    #pragma unroll
    for (int half = 0; half < 2; ++half) {
        float v = half ? v1 : v0;
        int o = 1;
        o += (v > -1.9459101f);
        o += (v > -1.0986123f);
        o += (v > -0.51082563f);
        o += (v > -0x1.8p-23f);      // exact fp32 crossover of sigmoid==0.5
        o += (v >  0.51082563f);
        o += (v >  1.0986123f);
        o += (v >  1.9459101f);
        out[row * 8 + q + 4 * half] = (float)o;
    }
}

// ============================================================================
extern "C" void kernel_launch(void* const* d_in, const int* in_sizes, int n_in,
                              void* d_out, int out_size)
{
    const float* state = nullptr; const float* W1 = nullptr; const float* b1 = nullptr;
    const float* W2 = nullptr;    const float* b2 = nullptr; const float* W3 = nullptr;
    const float* b3 = nullptr;    const float* eps = nullptr;

    for (int pass = 0; pass < 2 && !state; ++pass) {
        long long mul = (pass == 0) ? 1 : 4;
        state = W1 = b1 = W2 = b2 = W3 = b3 = eps = nullptr;
        for (int i = 0; i < n_in; ++i) {
            const float* p = (const float*)d_in[i];
            long long sz = (long long)in_sizes[i];
            if      (sz == 33554432LL * mul) state = p;
            else if (sz == 32768LL    * mul) W1 = p;
            else if (sz == 65536LL    * mul) W2 = p;
            else if (sz == 4096LL     * mul) W3 = p;
            else if (sz == 2097152LL  * mul) eps = p;
            else if (sz == 16LL       * mul) b3 = p;
            else if (sz == 256LL      * mul) { if (!b1) b1 = p; else b2 = p; }
        }
    }
    if (!state || !W1 || !b1 || !W2 || !b2 || !W3 || !b3 || !eps) {
        state = (const float*)d_in[0]; W1 = (const float*)d_in[1];
        b1    = (const float*)d_in[2]; W2 = (const float*)d_in[3];
        b2    = (const float*)d_in[4]; W3 = (const float*)d_in[5];
        b3    = (const float*)d_in[6]; eps = (const float*)d_in[7];
    }

    static bool attr_done = false;
    if (!attr_done) {
        cudaFuncSetAttribute(actor_fused,
                             cudaFuncAttributeMaxDynamicSharedMemorySize, SMEM_TOTAL);
        attr_done = true;
    }

    prep_w<<<NBLK, 256>>>(W1, W2);
    actor_fused<<<NT, 256, SMEM_TOTAL>>>(state, b1, b2, W3, b3, eps, (float*)d_out);
}